// round 7
// baseline (speedup 1.0000x reference)
#include <cuda_runtime.h>
#include <cuda_bf16.h>
#include <cstdint>
#include <cstddef>

#define BB     8
#define TT     256
#define NEN    64
#define HH     512
#define HD     128
#define VOCAB  32000
#define NROWS  (BB*TT)
#define LDO    (VOCAB+NEN)
#define GRIDN  128

__device__ float g_K[BB*NEN*HH];
__device__ float g_V[BB*NEN*HH];
__device__ float g_P[4*512*HH];          // P[h][(b*64+n)][j]
__device__ float g_Wqt[HH*HH];           // Wq transposed
__device__ float g_kseq[(size_t)NROWS*HH]; // gathered emb rows [b*TT+t][512]
__device__ float g_hx[BB*HH];
__device__ float g_cx[BB*HH];
__device__ float g_a[BB*HH];
__device__ float g_l[(size_t)NROWS*2*HH];
__device__ float g_dec[(size_t)NROWS*HH];
__device__ float g_s[NROWS];
__device__ float g_rowsum[NROWS];
__device__ float g_c[NROWS];
__device__ unsigned g_c1, g_c2;
__device__ __nv_bfloat16 g_Wb[(size_t)VOCAB*1024];
__device__ __nv_bfloat16 g_lb[(size_t)NROWS*1024];
__device__ __nv_bfloat16 g_logb[(size_t)NROWS*VOCAB];

__device__ __forceinline__ float sigf(float x) { return 1.0f / (1.0f + __expf(-x)); }

__device__ __forceinline__ float fexp(float x) {
    float z = x * 1.44269504088896f;
    float r = z + 12582912.0f;
    int   n = __float_as_int(r) - 0x4B400000;
    float f = z - (r - 12582912.0f);
    float p = 1.33336498e-3f;
    p = fmaf(p, f, 9.61011474e-3f);
    p = fmaf(p, f, 5.55036190e-2f);
    p = fmaf(p, f, 2.40226337e-1f);
    p = fmaf(p, f, 6.93147182e-1f);
    p = fmaf(p, f, 1.0f);
    return p * __int_as_float((n + 127) << 23);
}

__device__ __forceinline__ void red_add(unsigned* p) {
    asm volatile("red.release.gpu.global.add.u32 [%0], 1;" :: "l"(p) : "memory");
}
__device__ __forceinline__ unsigned ld_acq(unsigned* p) {
    unsigned v;
    asm volatile("ld.acquire.gpu.global.u32 %0, [%1];" : "=r"(v) : "l"(p) : "memory");
    return v;
}
__device__ __forceinline__ float4 ldcg4(const float* p) {
    float4 v;
    asm volatile("ld.global.cg.v4.f32 {%0,%1,%2,%3}, [%4];"
                 : "=f"(v.x), "=f"(v.y), "=f"(v.z), "=f"(v.w) : "l"(p));
    return v;
}

__global__ void k_init(const float* __restrict__ ents) {
    int blk = blockIdx.x;
    if (blk == 0 && threadIdx.x == 0) { g_c1 = 0u; g_c2 = 0u; }
    if (blk < BB) {
        int b = blk, h = threadIdx.x;
        float s = 0.f;
        #pragma unroll 8
        for (int n = 0; n < NEN; n++) s += ents[(size_t)(b*NEN + n)*HH + h];
        s *= (1.0f / NEN);
        g_hx[b*HH + h] = s;
        g_cx[b*HH + h] = s;
        g_a [b*HH + h] = 0.f;
    } else {
        int i = (blk - BB)*512 + threadIdx.x;
        if (i < NROWS) g_rowsum[i] = 0.f;
    }
}

__global__ __launch_bounds__(128) void k_gather(
    const float* __restrict__ emb, const int* __restrict__ outp)
{
    int r = blockIdx.x;
    int tok = __ldg(&outp[r]);
    const float4* src = (const float4*)(emb + (size_t)tok*HH);
    float4* dst = (float4*)(g_kseq + (size_t)r*HH);
    dst[threadIdx.x] = __ldg(&src[threadIdx.x]);
}

__global__ __launch_bounds__(256) void k_cvtw(const float* __restrict__ W) {
    size_t i = ((size_t)blockIdx.x*256 + threadIdx.x)*4;
    float4 v = *(const float4*)&W[i];
    __nv_bfloat162 p0 = __nv_bfloat162(__float2bfloat16(v.x), __float2bfloat16(v.y));
    __nv_bfloat162 p1 = __nv_bfloat162(__float2bfloat16(v.z), __float2bfloat16(v.w));
    *(__nv_bfloat162*)&g_Wb[i]   = p0;
    *(__nv_bfloat162*)&g_Wb[i+2] = p1;
}

__global__ void k_transp(const float* __restrict__ Wq) {
    __shared__ float t[32][33];
    int bx = blockIdx.x*32, by = blockIdx.y*32;
    int x = threadIdx.x, y = threadIdx.y;
    #pragma unroll
    for (int i = 0; i < 32; i += 8)
        t[y+i][x] = Wq[(size_t)(by + y + i)*HH + bx + x];
    __syncthreads();
    #pragma unroll
    for (int i = 0; i < 32; i += 8)
        g_Wqt[(size_t)(bx + y + i)*HH + by + x] = t[x][y+i];
}

// generic fp32 SGEMM: C[M,N] = A[M,K]@Bm[N,K]^T + bias, with z-batch offsets
__global__ __launch_bounds__(256) void k_sgemm(
    const float* __restrict__ A, int lda, int zA,
    const float* __restrict__ Bm, int ldb, int zB,
    const float* __restrict__ bias, float* __restrict__ C, int ldc, int zC,
    int Kdim)
{
    __shared__ float As[16][128];
    __shared__ float Bs[16][128];
    const float* Ab = A + (size_t)blockIdx.z*zA;
    const float* Bb = Bm + (size_t)blockIdx.z*zB;
    float* Cb = C + (size_t)blockIdx.z*zC;
    int m0 = blockIdx.y * 128, n0 = blockIdx.x * 128;
    int tid = threadIdx.x;
    int tx = tid & 15, ty = tid >> 4;
    int lr = tid >> 2, lc = tid & 3;
    float acc[8][8];
    #pragma unroll
    for (int i = 0; i < 8; i++)
        #pragma unroll
        for (int j = 0; j < 8; j++) acc[i][j] = 0.f;

    for (int k0 = 0; k0 < Kdim; k0 += 16) {
        #pragma unroll
        for (int i = 0; i < 2; i++) {
            float4 a4 = *(const float4*)&Ab[(size_t)(m0 + lr + 64*i)*lda + k0 + lc*4];
            As[lc*4+0][lr+64*i] = a4.x; As[lc*4+1][lr+64*i] = a4.y;
            As[lc*4+2][lr+64*i] = a4.z; As[lc*4+3][lr+64*i] = a4.w;
            float4 b4 = *(const float4*)&Bb[(size_t)(n0 + lr + 64*i)*ldb + k0 + lc*4];
            Bs[lc*4+0][lr+64*i] = b4.x; Bs[lc*4+1][lr+64*i] = b4.y;
            Bs[lc*4+2][lr+64*i] = b4.z; Bs[lc*4+3][lr+64*i] = b4.w;
        }
        __syncthreads();
        #pragma unroll
        for (int kk = 0; kk < 16; kk++) {
            float a[8], b[8];
            *(float4*)&a[0] = *(const float4*)&As[kk][ty*8];
            *(float4*)&a[4] = *(const float4*)&As[kk][ty*8+4];
            *(float4*)&b[0] = *(const float4*)&Bs[kk][tx*8];
            *(float4*)&b[4] = *(const float4*)&Bs[kk][tx*8+4];
            #pragma unroll
            for (int i = 0; i < 8; i++)
                #pragma unroll
                for (int j = 0; j < 8; j++)
                    acc[i][j] = fmaf(a[i], b[j], acc[i][j]);
        }
        __syncthreads();
    }
    #pragma unroll
    for (int i = 0; i < 8; i++) {
        int m = m0 + ty*8 + i;
        #pragma unroll
        for (int jv = 0; jv < 2; jv++) {
            int n = n0 + tx*8 + jv*4;
            float4 v;
            v.x = acc[i][jv*4+0]; v.y = acc[i][jv*4+1];
            v.z = acc[i][jv*4+2]; v.w = acc[i][jv*4+3];
            if (bias) {
                float4 bv = *(const float4*)&bias[n];
                v.x += bv.x; v.y += bv.y; v.z += bv.z; v.w += bv.w;
            }
            *(float4*)&Cb[(size_t)m*ldc + n] = v;
        }
    }
}

// ---------------- bf16 tensor-core logits GEMM + fused exp-rowsum ------------
#define PADK 40

__device__ __forceinline__ void ldsm4(uint32_t& r0, uint32_t& r1, uint32_t& r2, uint32_t& r3, uint32_t addr) {
    asm volatile("ldmatrix.sync.aligned.m8n8.x4.shared.b16 {%0,%1,%2,%3}, [%4];"
                 : "=r"(r0), "=r"(r1), "=r"(r2), "=r"(r3) : "r"(addr));
}
__device__ __forceinline__ void mma16816(float* c, const uint32_t* a, const uint32_t* b) {
    asm volatile("mma.sync.aligned.m16n8k16.row.col.f32.bf16.bf16.f32 "
                 "{%0,%1,%2,%3}, {%4,%5,%6,%7}, {%8,%9}, {%0,%1,%2,%3};"
                 : "+f"(c[0]), "+f"(c[1]), "+f"(c[2]), "+f"(c[3])
                 : "r"(a[0]), "r"(a[1]), "r"(a[2]), "r"(a[3]), "r"(b[0]), "r"(b[1]));
}

__global__ __launch_bounds__(256) void k_logits_mma(const float* __restrict__ bias)
{
    __shared__ __nv_bfloat16 As[2][128*PADK];
    __shared__ __nv_bfloat16 Bs[2][128*PADK];
    __shared__ float rsum[128];
    const int Kd = 1024;
    const __nv_bfloat16* A = g_lb;
    const __nv_bfloat16* B = g_Wb;
    int m0 = blockIdx.y*128, n0 = blockIdx.x*128;
    int tid = threadIdx.x;
    int warp = tid >> 5, lane = tid & 31;
    int wm = warp >> 2, wn = warp & 3;

    int srow = tid & 127;
    int shalf = tid >> 7;
    const __nv_bfloat16* gA = A + (size_t)(m0 + srow)*Kd + shalf*16;
    const __nv_bfloat16* gB = B + (size_t)(n0 + srow)*Kd + shalf*16;
    uint32_t sA0 = (uint32_t)__cvta_generic_to_shared(&As[0][srow*PADK + shalf*16]);
    uint32_t sB0 = (uint32_t)__cvta_generic_to_shared(&Bs[0][srow*PADK + shalf*16]);
    const uint32_t bufstrideA = (uint32_t)((char*)&As[1][0] - (char*)&As[0][0]);
    const uint32_t bufstrideB = (uint32_t)((char*)&Bs[1][0] - (char*)&Bs[0][0]);

    float acc[4][4][4];
    #pragma unroll
    for (int i = 0; i < 4; i++)
        #pragma unroll
        for (int j = 0; j < 4; j++)
            #pragma unroll
            for (int k = 0; k < 4; k++) acc[i][j][k] = 0.f;

    int aq = lane >> 3;
    int arow_off = ((aq & 1) << 3) + (lane & 7);
    int acol_off = (aq >> 1) << 3;
    int brow_off = ((aq >> 1) << 3) + (lane & 7);
    int bcol_off = (aq & 1) << 3;

    #pragma unroll
    for (int s = 0; s < 2; s++) {
        asm volatile("cp.async.cg.shared.global [%0], [%1], 16;" ::
                     "r"(sA0 + s*16), "l"(gA + s*8));
        asm volatile("cp.async.cg.shared.global [%0], [%1], 16;" ::
                     "r"(sB0 + s*16), "l"(gB + s*8));
    }
    asm volatile("cp.async.commit_group;");

    const int NIT = Kd/32;
    for (int it = 0; it < NIT; it++) {
        int buf = it & 1;
        if (it + 1 < NIT) {
            uint32_t sa = sA0 + ((it+1)&1)*bufstrideA;
            uint32_t sb = sB0 + ((it+1)&1)*bufstrideB;
            const __nv_bfloat16* ga = gA + (it+1)*32;
            const __nv_bfloat16* gb = gB + (it+1)*32;
            #pragma unroll
            for (int s = 0; s < 2; s++) {
                asm volatile("cp.async.cg.shared.global [%0], [%1], 16;" ::
                             "r"(sa + s*16), "l"(ga + s*8));
                asm volatile("cp.async.cg.shared.global [%0], [%1], 16;" ::
                             "r"(sb + s*16), "l"(gb + s*8));
            }
            asm volatile("cp.async.commit_group;");
            asm volatile("cp.async.wait_group 1;");
        } else {
            asm volatile("cp.async.wait_group 0;");
        }
        __syncthreads();

        #pragma unroll
        for (int kk = 0; kk < 2; kk++) {
            uint32_t aF[4][4], bF[4][2];
            #pragma unroll
            for (int mi = 0; mi < 4; mi++) {
                int row = wm*64 + mi*16 + arow_off;
                int col = kk*16 + acol_off;
                uint32_t ad = (uint32_t)__cvta_generic_to_shared(&As[buf][row*PADK + col]);
                ldsm4(aF[mi][0], aF[mi][1], aF[mi][2], aF[mi][3], ad);
            }
            #pragma unroll
            for (int np = 0; np < 2; np++) {
                int row = wn*32 + np*16 + brow_off;
                int col = kk*16 + bcol_off;
                uint32_t bd = (uint32_t)__cvta_generic_to_shared(&Bs[buf][row*PADK + col]);
                ldsm4(bF[np*2][0], bF[np*2][1], bF[np*2+1][0], bF[np*2+1][1], bd);
            }
            #pragma unroll
            for (int mi = 0; mi < 4; mi++)
                #pragma unroll
                for (int ni = 0; ni < 4; ni++)
                    mma16816(acc[mi][ni], aF[mi], bF[ni]);
        }
        __syncthreads();
    }

    if (tid < 128) rsum[tid] = 0.f;
    __syncthreads();

    int g = lane >> 2, tg = lane & 3;
    #pragma unroll
    for (int mi = 0; mi < 4; mi++) {
        int r0l = wm*64 + mi*16 + g;
        int r1l = r0l + 8;
        float rp0 = 0.f, rp1 = 0.f;
        #pragma unroll
        for (int ni = 0; ni < 4; ni++) {
            int n = n0 + wn*32 + ni*8 + tg*2;
            float2 bv = *(const float2*)&bias[n];
            float v0 = acc[mi][ni][0] + bv.x;
            float v1 = acc[mi][ni][1] + bv.y;
            float v2 = acc[mi][ni][2] + bv.x;
            float v3 = acc[mi][ni][3] + bv.y;
            *(__nv_bfloat162*)&g_logb[(size_t)(m0 + r0l)*VOCAB + n] =
                __nv_bfloat162(__float2bfloat16(v0), __float2bfloat16(v1));
            *(__nv_bfloat162*)&g_logb[(size_t)(m0 + r1l)*VOCAB + n] =
                __nv_bfloat162(__float2bfloat16(v2), __float2bfloat16(v3));
            rp0 += fexp(v0) + fexp(v1);
            rp1 += fexp(v2) + fexp(v3);
        }
        atomicAdd(&rsum[r0l], rp0);
        atomicAdd(&rsum[r1l], rp1);
    }
    __syncthreads();
    if (tid < 128) atomicAdd(&g_rowsum[m0 + tid], rsum[tid]);
}

// ---------------- persistent recurrence kernel (pipelined) -------------------
// blocks 0-95: LSTM. Per step: partial gates (k,hx) BEFORE waiting on a(t-1),
// then the a-part + cell update. blocks 96-127: attention (L1-resident P, V).
// c1 counts LSTM completions (96/step); c2 counts attention completions (32/step).
__global__ __launch_bounds__(256) void k_recur(
    const float* __restrict__ W_ih, const float* __restrict__ W_hh,
    const float* __restrict__ b_ih, const float* __restrict__ b_hh,
    const int* __restrict__ entlens)
{
    extern __shared__ float sx[];
    float* sa  = sx;               // 8*512
    float* sk  = sx + 4096;        // 8*512
    float* sh  = sx + 8192;        // 8*512
    float* gsh = sx + 12288;       // 192
    __shared__ float cxs[48];
    __shared__ float sc[NEN];

    int tid = threadIdx.x;
    int blk = blockIdx.x;
    int warp = tid >> 5, lane = tid & 31;
    bool isAtt = (blk >= 96);

    int ng = 0, g0 = 0;
    const float4 *wa0=nullptr,*wa1=nullptr,*wa2=nullptr,*wb0=nullptr,*wb1=nullptr,*wb2=nullptr;
    float bias0=0.f, bias1=0.f, bias2=0.f;
    bool has2 = false;
    int ab = 0, ah = 0, alen = 0;

    if (!isAtt) {
        ng = (blk < 32) ? 6 : 5;
        g0 = (blk < 32) ? blk*6 : 192 + (blk - 32)*5;
        int nrows = 4*ng;
        int lr0 = warp, lr1 = warp + 8, lr2 = warp + 16;
        has2 = (lr2 < nrows);
        int r0 = (lr0 & 3)*512 + g0 + (lr0 >> 2);
        int r1 = (lr1 & 3)*512 + g0 + (lr1 >> 2);
        int r2 = has2 ? ((lr2 & 3)*512 + g0 + (lr2 >> 2)) : r0;
        wa0 = (const float4*)(W_ih + (size_t)r0*1024);
        wa1 = (const float4*)(W_ih + (size_t)r1*1024);
        wa2 = (const float4*)(W_ih + (size_t)r2*1024);
        wb0 = (const float4*)(W_hh + (size_t)r0*512);
        wb1 = (const float4*)(W_hh + (size_t)r1*512);
        wb2 = (const float4*)(W_hh + (size_t)r2*512);
        bias0 = b_ih[r0] + b_hh[r0];
        bias1 = b_ih[r1] + b_hh[r1];
        bias2 = has2 ? (b_ih[r2] + b_hh[r2]) : 0.f;
        if (tid < ng*8)
            cxs[tid] = g_cx[(tid & 7)*HH + g0 + (tid >> 3)];
    } else {
        ab = (blk - 96) >> 2;
        ah = (blk - 96) & 3;
        alen = __ldg(&entlens[ab]);
    }

    if (!isAtt) {
        unsigned c1t = 0, c2t = 0;
        for (int t = 0; t < TT; t++) {
            // wait for all LSTM blocks to finish previous step (hx complete)
            if (t) {
                if (tid == 0) { while (ld_acq(&g_c1) < c1t) __nanosleep(32); }
                __syncthreads();
            }
            // stage hx(t-1) and k(t)
            for (int i = tid; i < 1024; i += 256) {
                int b = i >> 7, j = i & 127;
                ((float4*)sh)[i] = ldcg4(g_hx + (size_t)b*HH + j*4);
                ((float4*)sk)[i] = __ldg(((const float4*)(g_kseq + (size_t)(b*TT + t)*HH)) + j);
            }
            __syncthreads();

            float acc0[8], acc1[8], acc2[8];
            #pragma unroll
            for (int b = 0; b < 8; b++) { acc0[b] = 0.f; acc1[b] = 0.f; acc2[b] = 0.f; }

            // partial: k part (W_ih cols 512..1023)
            #pragma unroll
            for (int i = 0; i < 4; i++) {
                float4 w0 = wa0[128 + i*32 + lane];
                float4 w1 = wa1[128 + i*32 + lane];
                float4 w2 = wa2[128 + i*32 + lane];
                #pragma unroll
                for (int b = 0; b < 8; b++) {
                    float4 x = *(const float4*)&sk[b*512 + ((i*32 + lane) << 2)];
                    acc0[b] = fmaf(w0.x,x.x, fmaf(w0.y,x.y, fmaf(w0.z,x.z, fmaf(w0.w,x.w, acc0[b]))));
                    acc1[b] = fmaf(w1.x,x.x, fmaf(w1.y,x.y, fmaf(w1.z,x.z, fmaf(w1.w,x.w, acc1[b]))));
                    acc2[b] = fmaf(w2.x,x.x, fmaf(w2.y,x.y, fmaf(w2.z,x.z, fmaf(w2.w,x.w, acc2[b]))));
                }
            }
            // partial: hx part (W_hh)
            #pragma unroll
            for (int i = 0; i < 4; i++) {
                float4 w0 = wb0[i*32 + lane];
                float4 w1 = wb1[i*32 + lane];
                float4 w2 = wb2[i*32 + lane];
                #pragma unroll
                for (int b = 0; b < 8; b++) {
                    float4 x = *(const float4*)&sh[b*512 + ((i*32 + lane) << 2)];
                    acc0[b] = fmaf(w0.x,x.x, fmaf(w0.y,x.y, fmaf(w0.z,x.z, fmaf(w0.w,x.w, acc0[b]))));
                    acc1[b] = fmaf(w1.x,x.x, fmaf(w1.y,x.y, fmaf(w1.z,x.z, fmaf(w1.w,x.w, acc1[b]))));
                    acc2[b] = fmaf(w2.x,x.x, fmaf(w2.y,x.y, fmaf(w2.z,x.z, fmaf(w2.w,x.w, acc2[b]))));
                }
            }

            // wait for attention a(t-1), then stage it
            if (t) {
                if (tid == 0) { while (ld_acq(&g_c2) < c2t) __nanosleep(32); }
            }
            __syncthreads();
            for (int i = tid; i < 1024; i += 256) {
                int b = i >> 7, j = i & 127;
                ((float4*)sa)[i] = ldcg4(g_a + (size_t)b*HH + j*4);
            }
            __syncthreads();

            // final: a part (W_ih cols 0..511)
            #pragma unroll
            for (int i = 0; i < 4; i++) {
                float4 w0 = wa0[i*32 + lane];
                float4 w1 = wa1[i*32 + lane];
                float4 w2 = wa2[i*32 + lane];
                #pragma unroll
                for (int b = 0; b < 8; b++) {
                    float4 x = *(const float4*)&sa[b*512 + ((i*32 + lane) << 2)];
                    acc0[b] = fmaf(w0.x,x.x, fmaf(w0.y,x.y, fmaf(w0.z,x.z, fmaf(w0.w,x.w, acc0[b]))));
                    acc1[b] = fmaf(w1.x,x.x, fmaf(w1.y,x.y, fmaf(w1.z,x.z, fmaf(w1.w,x.w, acc1[b]))));
                    acc2[b] = fmaf(w2.x,x.x, fmaf(w2.y,x.y, fmaf(w2.z,x.z, fmaf(w2.w,x.w, acc2[b]))));
                }
            }
            #pragma unroll
            for (int b = 0; b < 8; b++) {
                float v0 = acc0[b], v1 = acc1[b], v2 = acc2[b];
                #pragma unroll
                for (int o = 16; o; o >>= 1) {
                    v0 += __shfl_xor_sync(0xffffffffu, v0, o);
                    v1 += __shfl_xor_sync(0xffffffffu, v1, o);
                    v2 += __shfl_xor_sync(0xffffffffu, v2, o);
                }
                if (lane == 0) {
                    gsh[warp*8 + b]     = v0 + bias0;
                    gsh[(warp+8)*8 + b] = v1 + bias1;
                    if (has2) gsh[(warp+16)*8 + b] = v2 + bias2;
                }
            }
            __syncthreads();
            if (tid < ng*8) {
                int lg = tid >> 3, b = tid & 7;
                int h = g0 + lg;
                float gi = gsh[(lg*4 + 0)*8 + b];
                float gf = gsh[(lg*4 + 1)*8 + b];
                float gg = gsh[(lg*4 + 2)*8 + b];
                float go = gsh[(lg*4 + 3)*8 + b];
                float c  = sigf(gf)*cxs[tid] + sigf(gi)*tanhf(gg);
                float hx = sigf(go)*tanhf(c);
                cxs[tid] = c;
                g_hx[b*HH + h] = hx;
                size_t li = ((size_t)(b*TT + t))*1024 + h;
                g_l[li]  = hx;
                g_lb[li] = __float2bfloat16(hx);
            }
            __syncthreads();
            if (tid == 0) red_add(&g_c1);
            c1t += 96; c2t += 32;
        }
    } else {
        unsigned c1t = 96;
        for (int t = 0; t < TT; t++) {
            if (tid == 0) { while (ld_acq(&g_c1) < c1t) __nanosleep(32); }
            __syncthreads();

            // stage hx(t) for our batch
            float* hxs = sh;   // reuse smem
            if (tid < 128)
                ((float4*)hxs)[tid] = ldcg4(g_hx + (size_t)ab*HH + tid*4);
            __syncthreads();

            {   // scores: 64 n x 4 threads
                int n = tid >> 2, sub = tid & 3;
                const float4* p4 = (const float4*)(g_P + ((size_t)(ah*512 + ab*64 + n))*512 + sub*128);
                const float4* x4 = (const float4*)(hxs + sub*128);
                float acc = 0.f;
                #pragma unroll 8
                for (int i = 0; i < 32; i++) {
                    float4 p = __ldg(&p4[i]), x = x4[i];
                    acc = fmaf(p.x,x.x, fmaf(p.y,x.y, fmaf(p.z,x.z, fmaf(p.w,x.w, acc))));
                }
                acc += __shfl_xor_sync(0xffffffffu, acc, 1);
                acc += __shfl_xor_sync(0xffffffffu, acc, 2);
                if (sub == 0)
                    sc[n] = (n <= alen) ? acc * 0.04419417382415922f : -1e30f;
            }
            __syncthreads();
            if (tid < 32) {
                float v0 = sc[tid], v1 = sc[tid + 32];
                float m = fmaxf(v0, v1);
                #pragma unroll
                for (int o = 16; o; o >>= 1) m = fmaxf(m, __shfl_xor_sync(0xffffffffu, m, o));
                float e0 = __expf(v0 - m), e1 = __expf(v1 - m);
                float s2 = e0 + e1;
                #pragma unroll
                for (int o = 16; o; o >>= 1) s2 += __shfl_xor_sync(0xffffffffu, s2, o);
                float inv = 1.0f / s2;
                sc[tid]      = e0 * inv;
                sc[tid + 32] = e1 * inv;
            }
            __syncthreads();
            {   // a = attn . V
                int d = tid >> 1, half = tid & 1;
                const float* vb = g_V + ((size_t)(ab*64 + half*32))*512 + ah*128 + d;
                float acc = 0.f;
                #pragma unroll 8
                for (int n2 = 0; n2 < 32; n2++)
                    acc = fmaf(sc[half*32 + n2], __ldg(&vb[(size_t)n2*512]), acc);
                float other = __shfl_xor_sync(0xffffffffu, acc, 1);
                if (half == 0) {
                    float av = acc + other;
                    int h = ah*128 + d;
                    g_a[ab*HH + h] = av;
                    size_t li = ((size_t)(ab*TT + t))*1024 + 512 + h;
                    g_l[li]  = av;
                    g_lb[li] = __float2bfloat16(av);
                }
            }
            __syncthreads();
            if (tid == 0) red_add(&g_c2);
            c1t += 96;
        }
    }
}

__global__ __launch_bounds__(256) void k_switch(
    const float* __restrict__ sw_W, const float* __restrict__ sw_b)
{
    int r = blockIdx.x*8 + (threadIdx.x >> 5);
    int lane = threadIdx.x & 31;
    const float4* l4 = (const float4*)(g_l + (size_t)r*1024);
    const float4* w4 = (const float4*)sw_W;
    float acc = 0.f;
    #pragma unroll
    for (int i = 0; i < 8; i++) {
        float4 a = l4[i*32 + lane], w = w4[i*32 + lane];
        acc = fmaf(a.x,w.x, fmaf(a.y,w.y, fmaf(a.z,w.z, fmaf(a.w,w.w, acc))));
    }
    #pragma unroll
    for (int o = 16; o; o >>= 1) acc += __shfl_xor_sync(0xffffffffu, acc, o);
    if (lane == 0) g_s[r] = sigf(acc + sw_b[0]);
}

__global__ __launch_bounds__(64) void k_ptr(
    const float* __restrict__ ents, const int* __restrict__ entlens,
    float* __restrict__ out, int write_tail)
{
    __shared__ float ds[HH];
    __shared__ float red[2];
    int r = blockIdx.x;
    int b = r >> 8;
    int tid = threadIdx.x;
    for (int i = tid; i < HH; i += 64) ds[i] = g_dec[(size_t)r*HH + i];
    __syncthreads();
    int len = entlens[b];
    float sv = -1e30f;
    if (tid <= len) {
        float acc = 0.f;
        const float4* e4 = (const float4*)(ents + (size_t)(b*NEN + tid)*HH);
        const float4* d4 = (const float4*)ds;
        #pragma unroll 8
        for (int i = 0; i < HH/4; i++) {
            float4 ev = e4[i], dv = d4[i];
            acc = fmaf(ev.x,dv.x, fmaf(ev.y,dv.y, fmaf(ev.z,dv.z, fmaf(ev.w,dv.w, acc))));
        }
        sv = acc;
    }
    float v = sv;
    #pragma unroll
    for (int o = 16; o; o >>= 1) v = fmaxf(v, __shfl_xor_sync(0xffffffffu, v, o));
    if ((tid & 31) == 0) red[tid >> 5] = v;
    __syncthreads();
    float m = fmaxf(red[0], red[1]);
    float e = (tid <= len) ? __expf(sv - m) : 0.f;
    float s2 = e;
    #pragma unroll
    for (int o = 16; o; o >>= 1) s2 += __shfl_xor_sync(0xffffffffu, s2, o);
    if ((tid & 31) == 0) red[tid >> 5] = s2;
    __syncthreads();
    float inv = 1.0f / (red[0] + red[1]);
    float s = g_s[r];
    float z = e * inv * (1.0f - s);
    out[(size_t)r*LDO + VOCAB + tid] = __logf(z + 1e-6f);
    if (write_tail) out[(size_t)NROWS*LDO + (size_t)r*NEN + tid] = z;
}

__global__ void k_rowc() {
    int r = blockIdx.x*256 + threadIdx.x;
    if (r < NROWS) g_c[r] = g_s[r] / g_rowsum[r];
}

__global__ __launch_bounds__(256) void k_final(float* __restrict__ out) {
    int r = blockIdx.x;
    float c = g_c[r];
    const __nv_bfloat162* src = (const __nv_bfloat162*)(g_logb + (size_t)r*VOCAB);
    float* dst = out + (size_t)r*LDO;
    for (int i = threadIdx.x; i < VOCAB/2; i += 256) {
        __nv_bfloat162 p = src[i];
        float2 o;
        o.x = __logf(fmaf(fexp(__bfloat162float(p.x)), c, 1e-6f));
        o.y = __logf(fmaf(fexp(__bfloat162float(p.y)), c, 1e-6f));
        *(float2*)&dst[i*2] = o;
    }
}

extern "C" void kernel_launch(void* const* d_in, const int* in_sizes, int n_in,
                              void* d_out, int out_size)
{
    const int*   outp    = (const int*)  d_in[0];
    const float* ents    = (const float*)d_in[1];
    const int*   entlens = (const int*)  d_in[2];
    const float* emb     = (const float*)d_in[3];
    const float* W_ih    = (const float*)d_in[4];
    const float* W_hh    = (const float*)d_in[5];
    const float* b_ih    = (const float*)d_in[6];
    const float* b_hh    = (const float*)d_in[7];
    const float* Wq      = (const float*)d_in[8];
    const float* Wk      = (const float*)d_in[9];
    const float* Wv      = (const float*)d_in[10];
    const float* out_W   = (const float*)d_in[11];
    const float* out_b   = (const float*)d_in[12];
    const float* sw_W    = (const float*)d_in[13];
    const float* sw_b    = (const float*)d_in[14];
    const float* mattn_W = (const float*)d_in[15];
    const float* mattn_b = (const float*)d_in[16];
    float* out = (float*)d_out;

    static int smem_set = 0;
    if (!smem_set) {
        cudaFuncSetAttribute(k_recur, cudaFuncAttributeMaxDynamicSharedMemorySize, 64*1024);
        smem_set = 1;
    }
    const int recur_smem = (3*4096 + 192) * 4;

    float *g_K_p, *g_V_p, *g_P_p, *g_Wqt_p, *g_l_p, *g_dec_p;
    cudaGetSymbolAddress((void**)&g_K_p, g_K);
    cudaGetSymbolAddress((void**)&g_V_p, g_V);
    cudaGetSymbolAddress((void**)&g_P_p, g_P);
    cudaGetSymbolAddress((void**)&g_Wqt_p, g_Wqt);
    cudaGetSymbolAddress((void**)&g_l_p, g_l);
    cudaGetSymbolAddress((void**)&g_dec_p, g_dec);

    k_init<<<12, 512>>>(ents);
    k_gather<<<NROWS, 128>>>(emb, outp);
    k_cvtw<<<VOCAB*1024/(256*4), 256>>>(out_W);
    k_transp<<<dim3(16,16), dim3(32,8)>>>(Wq);
    k_sgemm<<<dim3(4,4,1), 256>>>(ents, 512, 0, Wk, 512, 0, nullptr, g_K_p, 512, 0, 512);
    k_sgemm<<<dim3(4,4,1), 256>>>(ents, 512, 0, Wv, 512, 0, nullptr, g_V_p, 512, 0, 512);
    k_sgemm<<<dim3(4,4,4), 256>>>(g_K_p, 512, 128, g_Wqt_p, 512, 128, nullptr,
                                  g_P_p, 512, 512*512, 128);

    k_recur<<<GRIDN, 256, recur_smem>>>(W_ih, W_hh, b_ih, b_hh, entlens);

    k_switch<<<NROWS/8, 256>>>(sw_W, sw_b);
    k_sgemm<<<dim3(4,16,1), 256>>>(g_l_p, 1024, 0, mattn_W, 1024, 0, mattn_b,
                                   g_dec_p, 512, 0, 1024);
    k_logits_mma<<<dim3(VOCAB/128, NROWS/128), 256>>>(out_b);
    k_rowc<<<8, 256>>>();
    int write_tail = (out_size >= NROWS*LDO + NROWS*NEN) ? 1 : 0;
    k_ptr<<<NROWS, 64>>>(ents, entlens, out, write_tail);
    k_final<<<NROWS, 256>>>(out);
}

// round 8
// speedup vs baseline: 1.2953x; 1.2953x over previous
#include <cuda_runtime.h>
#include <cuda_bf16.h>
#include <cstdint>
#include <cstddef>

#define BB     8
#define TT     256
#define NEN    64
#define HH     512
#define HD     128
#define VOCAB  32000
#define NROWS  (BB*TT)
#define LDO    (VOCAB+NEN)
#define GRIDN  128

__device__ float g_K[BB*NEN*HH];
__device__ float g_V[BB*NEN*HH];
__device__ float g_P[4*512*HH];          // P[h][(b*64+n)][j]
__device__ float g_Wqt[HH*HH];
__device__ float g_kseq[(size_t)NROWS*HH];
__device__ float g_hx[BB*HH];
__device__ float g_cx[BB*HH];
__device__ float g_a[BB*HH];
__device__ float g_l[(size_t)NROWS*2*HH];
__device__ float g_dec[(size_t)NROWS*HH];
__device__ float g_s[NROWS];
__device__ float g_rowsum[NROWS];
__device__ float g_c[NROWS];
__device__ unsigned g_c1, g_c2;
__device__ __nv_bfloat16 g_Wb[(size_t)VOCAB*1024];
__device__ __nv_bfloat16 g_lb[(size_t)NROWS*1024];
__device__ __nv_bfloat16 g_logb[(size_t)NROWS*VOCAB];

__device__ __forceinline__ float sigf(float x) { return 1.0f / (1.0f + __expf(-x)); }

__device__ __forceinline__ float fexp(float x) {
    float z = x * 1.44269504088896f;
    float r = z + 12582912.0f;
    int   n = __float_as_int(r) - 0x4B400000;
    float f = z - (r - 12582912.0f);
    float p = 1.33336498e-3f;
    p = fmaf(p, f, 9.61011474e-3f);
    p = fmaf(p, f, 5.55036190e-2f);
    p = fmaf(p, f, 2.40226337e-1f);
    p = fmaf(p, f, 6.93147182e-1f);
    p = fmaf(p, f, 1.0f);
    return p * __int_as_float((n + 127) << 23);
}

// FMA-only natural log for x in (1e-7, 4): sqrt2-reduction + Taylor-8
__device__ __forceinline__ float flog(float x) {
    int xi = __float_as_int(x);
    int e = (xi >> 23) - 127;
    float m = __int_as_float((xi & 0x7FFFFF) | 0x3F800000);   // [1,2)
    if (m > 1.41421356f) { m *= 0.5f; e++; }
    float f = m - 1.0f;                                       // [-0.293, 0.414]
    float p = -0.125f;
    p = fmaf(p, f,  0.14285714f);
    p = fmaf(p, f, -0.16666667f);
    p = fmaf(p, f,  0.2f);
    p = fmaf(p, f, -0.25f);
    p = fmaf(p, f,  0.33333333f);
    p = fmaf(p, f, -0.5f);
    p = fmaf(p, f,  1.0f);
    p *= f;
    return fmaf((float)e, 0.69314718056f, p);
}

__device__ __forceinline__ void red_add(unsigned* p) {
    asm volatile("red.release.gpu.global.add.u32 [%0], 1;" :: "l"(p) : "memory");
}
// relaxed poll: L2-coherent, does NOT invalidate L1 (keeps weights/P/V resident)
__device__ __forceinline__ unsigned ld_poll(unsigned* p) {
    unsigned v;
    asm volatile("ld.relaxed.gpu.global.u32 %0, [%1];" : "=r"(v) : "l"(p) : "memory");
    return v;
}
__device__ __forceinline__ float4 ldcg4(const float* p) {
    float4 v;
    asm volatile("ld.global.cg.v4.f32 {%0,%1,%2,%3}, [%4];"
                 : "=f"(v.x), "=f"(v.y), "=f"(v.z), "=f"(v.w) : "l"(p));
    return v;
}

__global__ void k_init(const float* __restrict__ ents) {
    int blk = blockIdx.x;
    if (blk == 0 && threadIdx.x == 0) { g_c1 = 0u; g_c2 = 0u; }
    if (blk < BB) {
        int b = blk, h = threadIdx.x;
        float s = 0.f;
        #pragma unroll 8
        for (int n = 0; n < NEN; n++) s += ents[(size_t)(b*NEN + n)*HH + h];
        s *= (1.0f / NEN);
        g_hx[b*HH + h] = s;
        g_cx[b*HH + h] = s;
        g_a [b*HH + h] = 0.f;
    } else {
        int i = (blk - BB)*512 + threadIdx.x;
        if (i < NROWS) g_rowsum[i] = 0.f;
    }
}

__global__ __launch_bounds__(128) void k_gather(
    const float* __restrict__ emb, const int* __restrict__ outp)
{
    int r = blockIdx.x;
    int tok = __ldg(&outp[r]);
    const float4* src = (const float4*)(emb + (size_t)tok*HH);
    float4* dst = (float4*)(g_kseq + (size_t)r*HH);
    dst[threadIdx.x] = __ldg(&src[threadIdx.x]);
}

__global__ __launch_bounds__(256) void k_cvtw(const float* __restrict__ W) {
    size_t i = ((size_t)blockIdx.x*256 + threadIdx.x)*4;
    float4 v = *(const float4*)&W[i];
    __nv_bfloat162 p0 = __nv_bfloat162(__float2bfloat16(v.x), __float2bfloat16(v.y));
    __nv_bfloat162 p1 = __nv_bfloat162(__float2bfloat16(v.z), __float2bfloat16(v.w));
    *(__nv_bfloat162*)&g_Wb[i]   = p0;
    *(__nv_bfloat162*)&g_Wb[i+2] = p1;
}

__global__ void k_transp(const float* __restrict__ Wq) {
    __shared__ float t[32][33];
    int bx = blockIdx.x*32, by = blockIdx.y*32;
    int x = threadIdx.x, y = threadIdx.y;
    #pragma unroll
    for (int i = 0; i < 32; i += 8)
        t[y+i][x] = Wq[(size_t)(by + y + i)*HH + bx + x];
    __syncthreads();
    #pragma unroll
    for (int i = 0; i < 32; i += 8)
        g_Wqt[(size_t)(bx + y + i)*HH + by + x] = t[x][y+i];
}

__global__ __launch_bounds__(256) void k_sgemm(
    const float* __restrict__ A, int lda, int zA,
    const float* __restrict__ Bm, int ldb, int zB,
    const float* __restrict__ bias, float* __restrict__ C, int ldc, int zC,
    int Kdim)
{
    __shared__ float As[16][128];
    __shared__ float Bs[16][128];
    const float* Ab = A + (size_t)blockIdx.z*zA;
    const float* Bb = Bm + (size_t)blockIdx.z*zB;
    float* Cb = C + (size_t)blockIdx.z*zC;
    int m0 = blockIdx.y * 128, n0 = blockIdx.x * 128;
    int tid = threadIdx.x;
    int tx = tid & 15, ty = tid >> 4;
    int lr = tid >> 2, lc = tid & 3;
    float acc[8][8];
    #pragma unroll
    for (int i = 0; i < 8; i++)
        #pragma unroll
        for (int j = 0; j < 8; j++) acc[i][j] = 0.f;

    for (int k0 = 0; k0 < Kdim; k0 += 16) {
        #pragma unroll
        for (int i = 0; i < 2; i++) {
            float4 a4 = *(const float4*)&Ab[(size_t)(m0 + lr + 64*i)*lda + k0 + lc*4];
            As[lc*4+0][lr+64*i] = a4.x; As[lc*4+1][lr+64*i] = a4.y;
            As[lc*4+2][lr+64*i] = a4.z; As[lc*4+3][lr+64*i] = a4.w;
            float4 b4 = *(const float4*)&Bb[(size_t)(n0 + lr + 64*i)*ldb + k0 + lc*4];
            Bs[lc*4+0][lr+64*i] = b4.x; Bs[lc*4+1][lr+64*i] = b4.y;
            Bs[lc*4+2][lr+64*i] = b4.z; Bs[lc*4+3][lr+64*i] = b4.w;
        }
        __syncthreads();
        #pragma unroll
        for (int kk = 0; kk < 16; kk++) {
            float a[8], b[8];
            *(float4*)&a[0] = *(const float4*)&As[kk][ty*8];
            *(float4*)&a[4] = *(const float4*)&As[kk][ty*8+4];
            *(float4*)&b[0] = *(const float4*)&Bs[kk][tx*8];
            *(float4*)&b[4] = *(const float4*)&Bs[kk][tx*8+4];
            #pragma unroll
            for (int i = 0; i < 8; i++)
                #pragma unroll
                for (int j = 0; j < 8; j++)
                    acc[i][j] = fmaf(a[i], b[j], acc[i][j]);
        }
        __syncthreads();
    }
    #pragma unroll
    for (int i = 0; i < 8; i++) {
        int m = m0 + ty*8 + i;
        #pragma unroll
        for (int jv = 0; jv < 2; jv++) {
            int n = n0 + tx*8 + jv*4;
            float4 v;
            v.x = acc[i][jv*4+0]; v.y = acc[i][jv*4+1];
            v.z = acc[i][jv*4+2]; v.w = acc[i][jv*4+3];
            if (bias) {
                float4 bv = *(const float4*)&bias[n];
                v.x += bv.x; v.y += bv.y; v.z += bv.z; v.w += bv.w;
            }
            *(float4*)&Cb[(size_t)m*ldc + n] = v;
        }
    }
}

// ---------------- bf16 tensor-core logits GEMM + fused exp-rowsum ------------
#define PADK 40

__device__ __forceinline__ void ldsm4(uint32_t& r0, uint32_t& r1, uint32_t& r2, uint32_t& r3, uint32_t addr) {
    asm volatile("ldmatrix.sync.aligned.m8n8.x4.shared.b16 {%0,%1,%2,%3}, [%4];"
                 : "=r"(r0), "=r"(r1), "=r"(r2), "=r"(r3) : "r"(addr));
}
__device__ __forceinline__ void mma16816(float* c, const uint32_t* a, const uint32_t* b) {
    asm volatile("mma.sync.aligned.m16n8k16.row.col.f32.bf16.bf16.f32 "
                 "{%0,%1,%2,%3}, {%4,%5,%6,%7}, {%8,%9}, {%0,%1,%2,%3};"
                 : "+f"(c[0]), "+f"(c[1]), "+f"(c[2]), "+f"(c[3])
                 : "r"(a[0]), "r"(a[1]), "r"(a[2]), "r"(a[3]), "r"(b[0]), "r"(b[1]));
}

__global__ __launch_bounds__(256) void k_logits_mma(const float* __restrict__ bias)
{
    __shared__ __nv_bfloat16 As[2][128*PADK];
    __shared__ __nv_bfloat16 Bs[2][128*PADK];
    __shared__ float rsum[128];
    const int Kd = 1024;
    const __nv_bfloat16* A = g_lb;
    const __nv_bfloat16* B = g_Wb;
    int m0 = blockIdx.y*128, n0 = blockIdx.x*128;
    int tid = threadIdx.x;
    int warp = tid >> 5, lane = tid & 31;
    int wm = warp >> 2, wn = warp & 3;

    int srow = tid & 127;
    int shalf = tid >> 7;
    const __nv_bfloat16* gA = A + (size_t)(m0 + srow)*Kd + shalf*16;
    const __nv_bfloat16* gB = B + (size_t)(n0 + srow)*Kd + shalf*16;
    uint32_t sA0 = (uint32_t)__cvta_generic_to_shared(&As[0][srow*PADK + shalf*16]);
    uint32_t sB0 = (uint32_t)__cvta_generic_to_shared(&Bs[0][srow*PADK + shalf*16]);
    const uint32_t bufstrideA = (uint32_t)((char*)&As[1][0] - (char*)&As[0][0]);
    const uint32_t bufstrideB = (uint32_t)((char*)&Bs[1][0] - (char*)&Bs[0][0]);

    float acc[4][4][4];
    #pragma unroll
    for (int i = 0; i < 4; i++)
        #pragma unroll
        for (int j = 0; j < 4; j++)
            #pragma unroll
            for (int k = 0; k < 4; k++) acc[i][j][k] = 0.f;

    int aq = lane >> 3;
    int arow_off = ((aq & 1) << 3) + (lane & 7);
    int acol_off = (aq >> 1) << 3;
    int brow_off = ((aq >> 1) << 3) + (lane & 7);
    int bcol_off = (aq & 1) << 3;

    #pragma unroll
    for (int s = 0; s < 2; s++) {
        asm volatile("cp.async.cg.shared.global [%0], [%1], 16;" ::
                     "r"(sA0 + s*16), "l"(gA + s*8));
        asm volatile("cp.async.cg.shared.global [%0], [%1], 16;" ::
                     "r"(sB0 + s*16), "l"(gB + s*8));
    }
    asm volatile("cp.async.commit_group;");

    const int NIT = Kd/32;
    for (int it = 0; it < NIT; it++) {
        int buf = it & 1;
        if (it + 1 < NIT) {
            uint32_t sa = sA0 + ((it+1)&1)*bufstrideA;
            uint32_t sb = sB0 + ((it+1)&1)*bufstrideB;
            const __nv_bfloat16* ga = gA + (it+1)*32;
            const __nv_bfloat16* gb = gB + (it+1)*32;
            #pragma unroll
            for (int s = 0; s < 2; s++) {
                asm volatile("cp.async.cg.shared.global [%0], [%1], 16;" ::
                             "r"(sa + s*16), "l"(ga + s*8));
                asm volatile("cp.async.cg.shared.global [%0], [%1], 16;" ::
                             "r"(sb + s*16), "l"(gb + s*8));
            }
            asm volatile("cp.async.commit_group;");
            asm volatile("cp.async.wait_group 1;");
        } else {
            asm volatile("cp.async.wait_group 0;");
        }
        __syncthreads();

        #pragma unroll
        for (int kk = 0; kk < 2; kk++) {
            uint32_t aF[4][4], bF[4][2];
            #pragma unroll
            for (int mi = 0; mi < 4; mi++) {
                int row = wm*64 + mi*16 + arow_off;
                int col = kk*16 + acol_off;
                uint32_t ad = (uint32_t)__cvta_generic_to_shared(&As[buf][row*PADK + col]);
                ldsm4(aF[mi][0], aF[mi][1], aF[mi][2], aF[mi][3], ad);
            }
            #pragma unroll
            for (int np = 0; np < 2; np++) {
                int row = wn*32 + np*16 + brow_off;
                int col = kk*16 + bcol_off;
                uint32_t bd = (uint32_t)__cvta_generic_to_shared(&Bs[buf][row*PADK + col]);
                ldsm4(bF[np*2][0], bF[np*2][1], bF[np*2+1][0], bF[np*2+1][1], bd);
            }
            #pragma unroll
            for (int mi = 0; mi < 4; mi++)
                #pragma unroll
                for (int ni = 0; ni < 4; ni++)
                    mma16816(acc[mi][ni], aF[mi], bF[ni]);
        }
        __syncthreads();
    }

    if (tid < 128) rsum[tid] = 0.f;
    __syncthreads();

    int g = lane >> 2, tg = lane & 3;
    #pragma unroll
    for (int mi = 0; mi < 4; mi++) {
        int r0l = wm*64 + mi*16 + g;
        int r1l = r0l + 8;
        float rp0 = 0.f, rp1 = 0.f;
        #pragma unroll
        for (int ni = 0; ni < 4; ni++) {
            int n = n0 + wn*32 + ni*8 + tg*2;
            float2 bv = *(const float2*)&bias[n];
            float v0 = acc[mi][ni][0] + bv.x;
            float v1 = acc[mi][ni][1] + bv.y;
            float v2 = acc[mi][ni][2] + bv.x;
            float v3 = acc[mi][ni][3] + bv.y;
            *(__nv_bfloat162*)&g_logb[(size_t)(m0 + r0l)*VOCAB + n] =
                __nv_bfloat162(__float2bfloat16(v0), __float2bfloat16(v1));
            *(__nv_bfloat162*)&g_logb[(size_t)(m0 + r1l)*VOCAB + n] =
                __nv_bfloat162(__float2bfloat16(v2), __float2bfloat16(v3));
            rp0 += fexp(v0) + fexp(v1);
            rp1 += fexp(v2) + fexp(v3);
        }
        atomicAdd(&rsum[r0l], rp0);
        atomicAdd(&rsum[r1l], rp1);
    }
    __syncthreads();
    if (tid < 128) atomicAdd(&g_rowsum[m0 + tid], rsum[tid]);
}

// ---------------- persistent recurrence kernel -------------------------------
// blocks 0-95: LSTM (c1 += 1 each step end). blocks 96-127: attention
// (c2 += 1 each step end). Polls are ld.relaxed → L1 stays warm.
__global__ __launch_bounds__(256) void k_recur(
    const float* __restrict__ W_ih, const float* __restrict__ W_hh,
    const float* __restrict__ b_ih, const float* __restrict__ b_hh,
    const int* __restrict__ entlens)
{
    extern __shared__ float sx[];                 // [8][1536] + gsh[192]
    float* gsh = sx + 8*1536;
    __shared__ float cxs[48];
    __shared__ float hxs[HH];
    __shared__ float sc[NEN];

    int tid = threadIdx.x;
    int blk = blockIdx.x;
    int warp = tid >> 5, lane = tid & 31;
    bool isAtt = (blk >= 96);

    int ng = 0, g0 = 0;
    const float4 *wa0=nullptr,*wa1=nullptr,*wa2=nullptr,*wb0=nullptr,*wb1=nullptr,*wb2=nullptr;
    float bias0=0.f, bias1=0.f, bias2=0.f;
    bool has2 = false;
    int ab = 0, ah = 0, alen = 0;

    if (!isAtt) {
        ng = (blk < 32) ? 6 : 5;
        g0 = (blk < 32) ? blk*6 : 192 + (blk - 32)*5;
        int nrows = 4*ng;
        int lr0 = warp, lr1 = warp + 8, lr2 = warp + 16;
        has2 = (lr2 < nrows);
        int r0 = (lr0 & 3)*512 + g0 + (lr0 >> 2);
        int r1 = (lr1 & 3)*512 + g0 + (lr1 >> 2);
        int r2 = has2 ? ((lr2 & 3)*512 + g0 + (lr2 >> 2)) : r0;
        wa0 = (const float4*)(W_ih + (size_t)r0*1024);
        wa1 = (const float4*)(W_ih + (size_t)r1*1024);
        wa2 = (const float4*)(W_ih + (size_t)r2*1024);
        wb0 = (const float4*)(W_hh + (size_t)r0*512);
        wb1 = (const float4*)(W_hh + (size_t)r1*512);
        wb2 = (const float4*)(W_hh + (size_t)r2*512);
        bias0 = b_ih[r0] + b_hh[r0];
        bias1 = b_ih[r1] + b_hh[r1];
        bias2 = has2 ? (b_ih[r2] + b_hh[r2]) : 0.f;
        if (tid < ng*8)
            cxs[tid] = g_cx[(tid & 7)*HH + g0 + (tid >> 3)];
    } else {
        ab = (blk - 96) >> 2;
        ah = (blk - 96) & 3;
        alen = __ldg(&entlens[ab]);
    }

    if (!isAtt) {
        for (int t = 0; t < TT; t++) {
            // stage a(t-1), hx(t-1), k(t)
            for (int i = tid; i < BB*HH; i += 256) {
                int b = i >> 9, j = i & 511;
                sx[b*1536 + j]        = __ldcg(&g_a[i]);
                sx[b*1536 + 1024 + j] = __ldcg(&g_hx[i]);
                sx[b*1536 + 512  + j] = __ldg(&g_kseq[(size_t)(b*TT + t)*HH + j]);
            }
            __syncthreads();

            float acc0[8], acc1[8], acc2[8];
            #pragma unroll
            for (int b = 0; b < 8; b++) { acc0[b] = 0.f; acc1[b] = 0.f; acc2[b] = 0.f; }

            #pragma unroll
            for (int i = 0; i < 8; i++) {
                float4 w0 = wa0[i*32 + lane];
                float4 w1 = wa1[i*32 + lane];
                float4 w2 = wa2[i*32 + lane];
                #pragma unroll
                for (int b = 0; b < 8; b++) {
                    float4 x = *(const float4*)&sx[b*1536 + ((i*32 + lane) << 2)];
                    acc0[b] = fmaf(w0.x,x.x, fmaf(w0.y,x.y, fmaf(w0.z,x.z, fmaf(w0.w,x.w, acc0[b]))));
                    acc1[b] = fmaf(w1.x,x.x, fmaf(w1.y,x.y, fmaf(w1.z,x.z, fmaf(w1.w,x.w, acc1[b]))));
                    acc2[b] = fmaf(w2.x,x.x, fmaf(w2.y,x.y, fmaf(w2.z,x.z, fmaf(w2.w,x.w, acc2[b]))));
                }
            }
            #pragma unroll
            for (int i = 0; i < 4; i++) {
                float4 w0 = wb0[i*32 + lane];
                float4 w1 = wb1[i*32 + lane];
                float4 w2 = wb2[i*32 + lane];
                #pragma unroll
                for (int b = 0; b < 8; b++) {
                    float4 x = *(const float4*)&sx[b*1536 + 1024 + ((i*32 + lane) << 2)];
                    acc0[b] = fmaf(w0.x,x.x, fmaf(w0.y,x.y, fmaf(w0.z,x.z, fmaf(w0.w,x.w, acc0[b]))));
                    acc1[b] = fmaf(w1.x,x.x, fmaf(w1.y,x.y, fmaf(w1.z,x.z, fmaf(w1.w,x.w, acc1[b]))));
                    acc2[b] = fmaf(w2.x,x.x, fmaf(w2.y,x.y, fmaf(w2.z,x.z, fmaf(w2.w,x.w, acc2[b]))));
                }
            }
            #pragma unroll
            for (int b = 0; b < 8; b++) {
                float v0 = acc0[b], v1 = acc1[b], v2 = acc2[b];
                #pragma unroll
                for (int o = 16; o; o >>= 1) {
                    v0 += __shfl_xor_sync(0xffffffffu, v0, o);
                    v1 += __shfl_xor_sync(0xffffffffu, v1, o);
                    v2 += __shfl_xor_sync(0xffffffffu, v2, o);
                }
                if (lane == 0) {
                    gsh[warp*8 + b]     = v0 + bias0;
                    gsh[(warp+8)*8 + b] = v1 + bias1;
                    if (has2) gsh[(warp+16)*8 + b] = v2 + bias2;
                }
            }
            __syncthreads();
            if (tid < ng*8) {
                int lg = tid >> 3, b = tid & 7;
                int h = g0 + lg;
                float gi = gsh[(lg*4 + 0)*8 + b];
                float gf = gsh[(lg*4 + 1)*8 + b];
                float gg = gsh[(lg*4 + 2)*8 + b];
                float go = gsh[(lg*4 + 3)*8 + b];
                float c  = sigf(gf)*cxs[tid] + sigf(gi)*tanhf(gg);
                float hx = sigf(go)*tanhf(c);
                cxs[tid] = c;
                g_hx[b*HH + h] = hx;
                size_t li = ((size_t)(b*TT + t))*1024 + h;
                g_l[li]  = hx;
                g_lb[li] = __float2bfloat16(hx);
            }
            __syncthreads();
            if (tid == 0) red_add(&g_c1);
            // wait for attention(t) before staging a(t) next iteration
            if (t + 1 < TT) {
                if (tid == 0) { unsigned tgt = 32u*(t+1); while (ld_poll(&g_c2) < tgt) __nanosleep(32); }
                __syncthreads();
            }
        }
    } else {
        for (int t = 0; t < TT; t++) {
            if (tid == 0) { unsigned tgt = 96u*(t+1); while (ld_poll(&g_c1) < tgt) __nanosleep(32); }
            __syncthreads();

            for (int i = tid; i < 128; i += 256)
                ((float4*)hxs)[i] = ldcg4(g_hx + (size_t)ab*HH + i*4);
            __syncthreads();

            {   // scores: 64 n x 4 threads (P slice is L1-resident now)
                int n = tid >> 2, sub = tid & 3;
                const float4* p4 = (const float4*)(g_P + ((size_t)(ah*512 + ab*64 + n))*512 + sub*128);
                const float4* x4 = (const float4*)(hxs + sub*128);
                float acc = 0.f;
                #pragma unroll 8
                for (int i = 0; i < 32; i++) {
                    float4 p = __ldg(&p4[i]), x = x4[i];
                    acc = fmaf(p.x,x.x, fmaf(p.y,x.y, fmaf(p.z,x.z, fmaf(p.w,x.w, acc))));
                }
                acc += __shfl_xor_sync(0xffffffffu, acc, 1);
                acc += __shfl_xor_sync(0xffffffffu, acc, 2);
                if (sub == 0)
                    sc[n] = (n <= alen) ? acc * 0.04419417382415922f : -1e30f;
            }
            __syncthreads();
            if (tid < 32) {
                float v0 = sc[tid], v1 = sc[tid + 32];
                float m = fmaxf(v0, v1);
                #pragma unroll
                for (int o = 16; o; o >>= 1) m = fmaxf(m, __shfl_xor_sync(0xffffffffu, m, o));
                float e0 = __expf(v0 - m), e1 = __expf(v1 - m);
                float s2 = e0 + e1;
                #pragma unroll
                for (int o = 16; o; o >>= 1) s2 += __shfl_xor_sync(0xffffffffu, s2, o);
                float inv = 1.0f / s2;
                sc[tid]      = e0 * inv;
                sc[tid + 32] = e1 * inv;
            }
            __syncthreads();
            {   // a = attn . V (V slice L1-resident)
                int d = tid >> 1, half = tid & 1;
                const float* vb = g_V + ((size_t)(ab*64 + half*32))*512 + ah*128 + d;
                float acc = 0.f;
                #pragma unroll 8
                for (int n2 = 0; n2 < 32; n2++)
                    acc = fmaf(sc[half*32 + n2], __ldg(&vb[(size_t)n2*512]), acc);
                float other = __shfl_xor_sync(0xffffffffu, acc, 1);
                if (half == 0) {
                    float av = acc + other;
                    int h = ah*128 + d;
                    g_a[ab*HH + h] = av;
                    size_t li = ((size_t)(ab*TT + t))*1024 + 512 + h;
                    g_l[li]  = av;
                    g_lb[li] = __float2bfloat16(av);
                }
            }
            __syncthreads();
            if (tid == 0) red_add(&g_c2);
        }
    }
}

__global__ __launch_bounds__(256) void k_switch(
    const float* __restrict__ sw_W, const float* __restrict__ sw_b)
{
    int r = blockIdx.x*8 + (threadIdx.x >> 5);
    int lane = threadIdx.x & 31;
    const float4* l4 = (const float4*)(g_l + (size_t)r*1024);
    const float4* w4 = (const float4*)sw_W;
    float acc = 0.f;
    #pragma unroll
    for (int i = 0; i < 8; i++) {
        float4 a = l4[i*32 + lane], w = w4[i*32 + lane];
        acc = fmaf(a.x,w.x, fmaf(a.y,w.y, fmaf(a.z,w.z, fmaf(a.w,w.w, acc))));
    }
    #pragma unroll
    for (int o = 16; o; o >>= 1) acc += __shfl_xor_sync(0xffffffffu, acc, o);
    if (lane == 0) g_s[r] = sigf(acc + sw_b[0]);
}

__global__ __launch_bounds__(64) void k_ptr(
    const float* __restrict__ ents, const int* __restrict__ entlens,
    float* __restrict__ out, int write_tail)
{
    __shared__ float ds[HH];
    __shared__ float red[2];
    int r = blockIdx.x;
    int b = r >> 8;
    int tid = threadIdx.x;
    for (int i = tid; i < HH; i += 64) ds[i] = g_dec[(size_t)r*HH + i];
    __syncthreads();
    int len = entlens[b];
    float sv = -1e30f;
    if (tid <= len) {
        float acc = 0.f;
        const float4* e4 = (const float4*)(ents + (size_t)(b*NEN + tid)*HH);
        const float4* d4 = (const float4*)ds;
        #pragma unroll 8
        for (int i = 0; i < HH/4; i++) {
            float4 ev = e4[i], dv = d4[i];
            acc = fmaf(ev.x,dv.x, fmaf(ev.y,dv.y, fmaf(ev.z,dv.z, fmaf(ev.w,dv.w, acc))));
        }
        sv = acc;
    }
    float v = sv;
    #pragma unroll
    for (int o = 16; o; o >>= 1) v = fmaxf(v, __shfl_xor_sync(0xffffffffu, v, o));
    if ((tid & 31) == 0) red[tid >> 5] = v;
    __syncthreads();
    float m = fmaxf(red[0], red[1]);
    float e = (tid <= len) ? __expf(sv - m) : 0.f;
    float s2 = e;
    #pragma unroll
    for (int o = 16; o; o >>= 1) s2 += __shfl_xor_sync(0xffffffffu, s2, o);
    if ((tid & 31) == 0) red[tid >> 5] = s2;
    __syncthreads();
    float inv = 1.0f / (red[0] + red[1]);
    float s = g_s[r];
    float z = e * inv * (1.0f - s);
    out[(size_t)r*LDO + VOCAB + tid] = flog(z + 1e-6f);
    if (write_tail) out[(size_t)NROWS*LDO + (size_t)r*NEN + tid] = z;
}

__global__ void k_rowc() {
    int r = blockIdx.x*256 + threadIdx.x;
    if (r < NROWS) g_c[r] = g_s[r] / g_rowsum[r];
}

__global__ __launch_bounds__(256) void k_final(float* __restrict__ out) {
    int r = blockIdx.x;
    float c = g_c[r];
    const __nv_bfloat162* src = (const __nv_bfloat162*)(g_logb + (size_t)r*VOCAB);
    float* dst = out + (size_t)r*LDO;
    for (int i = threadIdx.x; i < VOCAB/2; i += 256) {
        __nv_bfloat162 p = src[i];
        float2 o;
        o.x = flog(fmaf(fexp(__bfloat162float(p.x)), c, 1e-6f));
        o.y = flog(fmaf(fexp(__bfloat162float(p.y)), c, 1e-6f));
        *(float2*)&dst[i*2] = o;
    }
}

extern "C" void kernel_launch(void* const* d_in, const int* in_sizes, int n_in,
                              void* d_out, int out_size)
{
    const int*   outp    = (const int*)  d_in[0];
    const float* ents    = (const float*)d_in[1];
    const int*   entlens = (const int*)  d_in[2];
    const float* emb     = (const float*)d_in[3];
    const float* W_ih    = (const float*)d_in[4];
    const float* W_hh    = (const float*)d_in[5];
    const float* b_ih    = (const float*)d_in[6];
    const float* b_hh    = (const float*)d_in[7];
    const float* Wq      = (const float*)d_in[8];
    const float* Wk      = (const float*)d_in[9];
    const float* Wv      = (const float*)d_in[10];
    const float* out_W   = (const float*)d_in[11];
    const float* out_b   = (const float*)d_in[12];
    const float* sw_W    = (const float*)d_in[13];
    const float* sw_b    = (const float*)d_in[14];
    const float* mattn_W = (const float*)d_in[15];
    const float* mattn_b = (const float*)d_in[16];
    float* out = (float*)d_out;

    static int smem_set = 0;
    if (!smem_set) {
        cudaFuncSetAttribute(k_recur, cudaFuncAttributeMaxDynamicSharedMemorySize, 64*1024);
        smem_set = 1;
    }
    const int recur_smem = (8*1536 + 192) * 4;

    float *g_K_p, *g_V_p, *g_P_p, *g_Wqt_p, *g_l_p, *g_dec_p;
    cudaGetSymbolAddress((void**)&g_K_p, g_K);
    cudaGetSymbolAddress((void**)&g_V_p, g_V);
    cudaGetSymbolAddress((void**)&g_P_p, g_P);
    cudaGetSymbolAddress((void**)&g_Wqt_p, g_Wqt);
    cudaGetSymbolAddress((void**)&g_l_p, g_l);
    cudaGetSymbolAddress((void**)&g_dec_p, g_dec);

    k_init<<<12, 512>>>(ents);
    k_gather<<<NROWS, 128>>>(emb, outp);
    k_cvtw<<<VOCAB*1024/(256*4), 256>>>(out_W);
    k_transp<<<dim3(16,16), dim3(32,8)>>>(Wq);
    k_sgemm<<<dim3(4,4,1), 256>>>(ents, 512, 0, Wk, 512, 0, nullptr, g_K_p, 512, 0, 512);
    k_sgemm<<<dim3(4,4,1), 256>>>(ents, 512, 0, Wv, 512, 0, nullptr, g_V_p, 512, 0, 512);
    k_sgemm<<<dim3(4,4,4), 256>>>(g_K_p, 512, 128, g_Wqt_p, 512, 128, nullptr,
                                  g_P_p, 512, 512*512, 128);

    k_recur<<<GRIDN, 256, recur_smem>>>(W_ih, W_hh, b_ih, b_hh, entlens);

    k_switch<<<NROWS/8, 256>>>(sw_W, sw_b);
    k_sgemm<<<dim3(4,16,1), 256>>>(g_l_p, 1024, 0, mattn_W, 1024, 0, mattn_b,
                                   g_dec_p, 512, 0, 1024);
    k_logits_mma<<<dim3(VOCAB/128, NROWS/128), 256>>>(out_b);
    k_rowc<<<8, 256>>>();
    int write_tail = (out_size >= NROWS*LDO + NROWS*NEN) ? 1 : 0;
    k_ptr<<<NROWS, 64>>>(ents, entlens, out, write_tail);
    k_final<<<NROWS, 256>>>(out);
}

// round 9
// speedup vs baseline: 1.5181x; 1.1720x over previous
#include <cuda_runtime.h>
#include <cuda_bf16.h>
#include <cstdint>
#include <cstddef>

#define BB     8
#define TT     256
#define NEN    64
#define HH     512
#define HD     128
#define VOCAB  32000
#define NROWS  (BB*TT)
#define LDO    (VOCAB+NEN)
#define GRIDN  128

__device__ float g_K[BB*NEN*HH];
__device__ float g_V[BB*NEN*HH];
__device__ float g_P[4*512*HH];          // P[h][(b*64+n)][j]
__device__ float g_Wqt[HH*HH];
__device__ float g_kseq[(size_t)NROWS*HH];
__device__ float g_hx2[2*BB*HH];         // double-buffered hx: buf = t&1
__device__ float g_cx[BB*HH];
__device__ float g_a[BB*HH];
__device__ float g_l[(size_t)NROWS*2*HH];
__device__ float g_dec[(size_t)NROWS*HH];
__device__ float g_s[NROWS];
__device__ float g_rowsum[NROWS];
__device__ float g_c[NROWS];
__device__ unsigned g_c1, g_c2;
__device__ __nv_bfloat16 g_Wb[(size_t)VOCAB*1024];
__device__ __nv_bfloat16 g_lb[(size_t)NROWS*1024];
__device__ __nv_bfloat16 g_logb[(size_t)NROWS*VOCAB];

__device__ __forceinline__ float sigf(float x) { return 1.0f / (1.0f + __expf(-x)); }

__device__ __forceinline__ float fexp(float x) {
    float z = x * 1.44269504088896f;
    float r = z + 12582912.0f;
    int   n = __float_as_int(r) - 0x4B400000;
    float f = z - (r - 12582912.0f);
    float p = 1.33336498e-3f;
    p = fmaf(p, f, 9.61011474e-3f);
    p = fmaf(p, f, 5.55036190e-2f);
    p = fmaf(p, f, 2.40226337e-1f);
    p = fmaf(p, f, 6.93147182e-1f);
    p = fmaf(p, f, 1.0f);
    return p * __int_as_float((n + 127) << 23);
}

// FMA-only natural log for x in (1e-7, 4)
__device__ __forceinline__ float flog(float x) {
    int xi = __float_as_int(x);
    int e = (xi >> 23) - 127;
    float m = __int_as_float((xi & 0x7FFFFF) | 0x3F800000);
    if (m > 1.41421356f) { m *= 0.5f; e++; }
    float f = m - 1.0f;
    float p = -0.125f;
    p = fmaf(p, f,  0.14285714f);
    p = fmaf(p, f, -0.16666667f);
    p = fmaf(p, f,  0.2f);
    p = fmaf(p, f, -0.25f);
    p = fmaf(p, f,  0.33333333f);
    p = fmaf(p, f, -0.5f);
    p = fmaf(p, f,  1.0f);
    p *= f;
    return fmaf((float)e, 0.69314718056f, p);
}

__device__ __forceinline__ void red_add(unsigned* p) {
    asm volatile("red.release.gpu.global.add.u32 [%0], 1;" :: "l"(p) : "memory");
}
__device__ __forceinline__ unsigned ld_poll(unsigned* p) {
    unsigned v;
    asm volatile("ld.relaxed.gpu.global.u32 %0, [%1];" : "=r"(v) : "l"(p) : "memory");
    return v;
}
__device__ __forceinline__ float4 ldcg4(const float* p) {
    float4 v;
    asm volatile("ld.global.cg.v4.f32 {%0,%1,%2,%3}, [%4];"
                 : "=f"(v.x), "=f"(v.y), "=f"(v.z), "=f"(v.w) : "l"(p));
    return v;
}

__global__ void k_init(const float* __restrict__ ents) {
    int blk = blockIdx.x;
    if (blk == 0 && threadIdx.x == 0) { g_c1 = 0u; g_c2 = 0u; }
    if (blk < BB) {
        int b = blk, h = threadIdx.x;
        float s = 0.f;
        #pragma unroll 8
        for (int n = 0; n < NEN; n++) s += ents[(size_t)(b*NEN + n)*HH + h];
        s *= (1.0f / NEN);
        g_hx2[BB*HH + b*HH + h] = s;   // parity-1 buffer = hx(-1)
        g_cx[b*HH + h] = s;
        g_a [b*HH + h] = 0.f;
    } else {
        int i = (blk - BB)*512 + threadIdx.x;
        if (i < NROWS) g_rowsum[i] = 0.f;
    }
}

__global__ __launch_bounds__(128) void k_gather(
    const float* __restrict__ emb, const int* __restrict__ outp)
{
    int r = blockIdx.x;
    int tok = __ldg(&outp[r]);
    const float4* src = (const float4*)(emb + (size_t)tok*HH);
    float4* dst = (float4*)(g_kseq + (size_t)r*HH);
    dst[threadIdx.x] = __ldg(&src[threadIdx.x]);
}

__global__ __launch_bounds__(256) void k_cvtw(const float* __restrict__ W) {
    size_t i = ((size_t)blockIdx.x*256 + threadIdx.x)*4;
    float4 v = *(const float4*)&W[i];
    __nv_bfloat162 p0 = __nv_bfloat162(__float2bfloat16(v.x), __float2bfloat16(v.y));
    __nv_bfloat162 p1 = __nv_bfloat162(__float2bfloat16(v.z), __float2bfloat16(v.w));
    *(__nv_bfloat162*)&g_Wb[i]   = p0;
    *(__nv_bfloat162*)&g_Wb[i+2] = p1;
}

__global__ void k_transp(const float* __restrict__ Wq) {
    __shared__ float t[32][33];
    int bx = blockIdx.x*32, by = blockIdx.y*32;
    int x = threadIdx.x, y = threadIdx.y;
    #pragma unroll
    for (int i = 0; i < 32; i += 8)
        t[y+i][x] = Wq[(size_t)(by + y + i)*HH + bx + x];
    __syncthreads();
    #pragma unroll
    for (int i = 0; i < 32; i += 8)
        g_Wqt[(size_t)(bx + y + i)*HH + by + x] = t[x][y+i];
}

__global__ __launch_bounds__(256) void k_sgemm(
    const float* __restrict__ A, int lda, int zA,
    const float* __restrict__ Bm, int ldb, int zB,
    const float* __restrict__ bias, float* __restrict__ C, int ldc, int zC,
    int Kdim)
{
    __shared__ float As[16][128];
    __shared__ float Bs[16][128];
    const float* Ab = A + (size_t)blockIdx.z*zA;
    const float* Bb = Bm + (size_t)blockIdx.z*zB;
    float* Cb = C + (size_t)blockIdx.z*zC;
    int m0 = blockIdx.y * 128, n0 = blockIdx.x * 128;
    int tid = threadIdx.x;
    int tx = tid & 15, ty = tid >> 4;
    int lr = tid >> 2, lc = tid & 3;
    float acc[8][8];
    #pragma unroll
    for (int i = 0; i < 8; i++)
        #pragma unroll
        for (int j = 0; j < 8; j++) acc[i][j] = 0.f;

    for (int k0 = 0; k0 < Kdim; k0 += 16) {
        #pragma unroll
        for (int i = 0; i < 2; i++) {
            float4 a4 = *(const float4*)&Ab[(size_t)(m0 + lr + 64*i)*lda + k0 + lc*4];
            As[lc*4+0][lr+64*i] = a4.x; As[lc*4+1][lr+64*i] = a4.y;
            As[lc*4+2][lr+64*i] = a4.z; As[lc*4+3][lr+64*i] = a4.w;
            float4 b4 = *(const float4*)&Bb[(size_t)(n0 + lr + 64*i)*ldb + k0 + lc*4];
            Bs[lc*4+0][lr+64*i] = b4.x; Bs[lc*4+1][lr+64*i] = b4.y;
            Bs[lc*4+2][lr+64*i] = b4.z; Bs[lc*4+3][lr+64*i] = b4.w;
        }
        __syncthreads();
        #pragma unroll
        for (int kk = 0; kk < 16; kk++) {
            float a[8], b[8];
            *(float4*)&a[0] = *(const float4*)&As[kk][ty*8];
            *(float4*)&a[4] = *(const float4*)&As[kk][ty*8+4];
            *(float4*)&b[0] = *(const float4*)&Bs[kk][tx*8];
            *(float4*)&b[4] = *(const float4*)&Bs[kk][tx*8+4];
            #pragma unroll
            for (int i = 0; i < 8; i++)
                #pragma unroll
                for (int j = 0; j < 8; j++)
                    acc[i][j] = fmaf(a[i], b[j], acc[i][j]);
        }
        __syncthreads();
    }
    #pragma unroll
    for (int i = 0; i < 8; i++) {
        int m = m0 + ty*8 + i;
        #pragma unroll
        for (int jv = 0; jv < 2; jv++) {
            int n = n0 + tx*8 + jv*4;
            float4 v;
            v.x = acc[i][jv*4+0]; v.y = acc[i][jv*4+1];
            v.z = acc[i][jv*4+2]; v.w = acc[i][jv*4+3];
            if (bias) {
                float4 bv = *(const float4*)&bias[n];
                v.x += bv.x; v.y += bv.y; v.z += bv.z; v.w += bv.w;
            }
            *(float4*)&Cb[(size_t)m*ldc + n] = v;
        }
    }
}

// ---------------- bf16 tensor-core logits GEMM + fused exp-rowsum ------------
#define PADK 40

__device__ __forceinline__ void ldsm4(uint32_t& r0, uint32_t& r1, uint32_t& r2, uint32_t& r3, uint32_t addr) {
    asm volatile("ldmatrix.sync.aligned.m8n8.x4.shared.b16 {%0,%1,%2,%3}, [%4];"
                 : "=r"(r0), "=r"(r1), "=r"(r2), "=r"(r3) : "r"(addr));
}
__device__ __forceinline__ void mma16816(float* c, const uint32_t* a, const uint32_t* b) {
    asm volatile("mma.sync.aligned.m16n8k16.row.col.f32.bf16.bf16.f32 "
                 "{%0,%1,%2,%3}, {%4,%5,%6,%7}, {%8,%9}, {%0,%1,%2,%3};"
                 : "+f"(c[0]), "+f"(c[1]), "+f"(c[2]), "+f"(c[3])
                 : "r"(a[0]), "r"(a[1]), "r"(a[2]), "r"(a[3]), "r"(b[0]), "r"(b[1]));
}

__global__ __launch_bounds__(256) void k_logits_mma(const float* __restrict__ bias)
{
    __shared__ __nv_bfloat16 As[2][128*PADK];
    __shared__ __nv_bfloat16 Bs[2][128*PADK];
    __shared__ float rsum[128];
    const int Kd = 1024;
    const __nv_bfloat16* A = g_lb;
    const __nv_bfloat16* B = g_Wb;
    int m0 = blockIdx.y*128, n0 = blockIdx.x*128;
    int tid = threadIdx.x;
    int warp = tid >> 5, lane = tid & 31;
    int wm = warp >> 2, wn = warp & 3;

    int srow = tid & 127;
    int shalf = tid >> 7;
    const __nv_bfloat16* gA = A + (size_t)(m0 + srow)*Kd + shalf*16;
    const __nv_bfloat16* gB = B + (size_t)(n0 + srow)*Kd + shalf*16;
    uint32_t sA0 = (uint32_t)__cvta_generic_to_shared(&As[0][srow*PADK + shalf*16]);
    uint32_t sB0 = (uint32_t)__cvta_generic_to_shared(&Bs[0][srow*PADK + shalf*16]);
    const uint32_t bufstrideA = (uint32_t)((char*)&As[1][0] - (char*)&As[0][0]);
    const uint32_t bufstrideB = (uint32_t)((char*)&Bs[1][0] - (char*)&Bs[0][0]);

    float acc[4][4][4];
    #pragma unroll
    for (int i = 0; i < 4; i++)
        #pragma unroll
        for (int j = 0; j < 4; j++)
            #pragma unroll
            for (int k = 0; k < 4; k++) acc[i][j][k] = 0.f;

    int aq = lane >> 3;
    int arow_off = ((aq & 1) << 3) + (lane & 7);
    int acol_off = (aq >> 1) << 3;
    int brow_off = ((aq >> 1) << 3) + (lane & 7);
    int bcol_off = (aq & 1) << 3;

    #pragma unroll
    for (int s = 0; s < 2; s++) {
        asm volatile("cp.async.cg.shared.global [%0], [%1], 16;" ::
                     "r"(sA0 + s*16), "l"(gA + s*8));
        asm volatile("cp.async.cg.shared.global [%0], [%1], 16;" ::
                     "r"(sB0 + s*16), "l"(gB + s*8));
    }
    asm volatile("cp.async.commit_group;");

    const int NIT = Kd/32;
    for (int it = 0; it < NIT; it++) {
        int buf = it & 1;
        if (it + 1 < NIT) {
            uint32_t sa = sA0 + ((it+1)&1)*bufstrideA;
            uint32_t sb = sB0 + ((it+1)&1)*bufstrideB;
            const __nv_bfloat16* ga = gA + (it+1)*32;
            const __nv_bfloat16* gb = gB + (it+1)*32;
            #pragma unroll
            for (int s = 0; s < 2; s++) {
                asm volatile("cp.async.cg.shared.global [%0], [%1], 16;" ::
                             "r"(sa + s*16), "l"(ga + s*8));
                asm volatile("cp.async.cg.shared.global [%0], [%1], 16;" ::
                             "r"(sb + s*16), "l"(gb + s*8));
            }
            asm volatile("cp.async.commit_group;");
            asm volatile("cp.async.wait_group 1;");
        } else {
            asm volatile("cp.async.wait_group 0;");
        }
        __syncthreads();

        #pragma unroll
        for (int kk = 0; kk < 2; kk++) {
            uint32_t aF[4][4], bF[4][2];
            #pragma unroll
            for (int mi = 0; mi < 4; mi++) {
                int row = wm*64 + mi*16 + arow_off;
                int col = kk*16 + acol_off;
                uint32_t ad = (uint32_t)__cvta_generic_to_shared(&As[buf][row*PADK + col]);
                ldsm4(aF[mi][0], aF[mi][1], aF[mi][2], aF[mi][3], ad);
            }
            #pragma unroll
            for (int np = 0; np < 2; np++) {
                int row = wn*32 + np*16 + brow_off;
                int col = kk*16 + bcol_off;
                uint32_t bd = (uint32_t)__cvta_generic_to_shared(&Bs[buf][row*PADK + col]);
                ldsm4(bF[np*2][0], bF[np*2][1], bF[np*2+1][0], bF[np*2+1][1], bd);
            }
            #pragma unroll
            for (int mi = 0; mi < 4; mi++)
                #pragma unroll
                for (int ni = 0; ni < 4; ni++)
                    mma16816(acc[mi][ni], aF[mi], bF[ni]);
        }
        __syncthreads();
    }

    if (tid < 128) rsum[tid] = 0.f;
    __syncthreads();

    int g = lane >> 2, tg = lane & 3;
    #pragma unroll
    for (int mi = 0; mi < 4; mi++) {
        int r0l = wm*64 + mi*16 + g;
        int r1l = r0l + 8;
        float rp0 = 0.f, rp1 = 0.f;
        #pragma unroll
        for (int ni = 0; ni < 4; ni++) {
            int n = n0 + wn*32 + ni*8 + tg*2;
            float2 bv = *(const float2*)&bias[n];
            float v0 = acc[mi][ni][0] + bv.x;
            float v1 = acc[mi][ni][1] + bv.y;
            float v2 = acc[mi][ni][2] + bv.x;
            float v3 = acc[mi][ni][3] + bv.y;
            *(__nv_bfloat162*)&g_logb[(size_t)(m0 + r0l)*VOCAB + n] =
                __nv_bfloat162(__float2bfloat16(v0), __float2bfloat16(v1));
            *(__nv_bfloat162*)&g_logb[(size_t)(m0 + r1l)*VOCAB + n] =
                __nv_bfloat162(__float2bfloat16(v2), __float2bfloat16(v3));
            rp0 += fexp(v0) + fexp(v1);
            rp1 += fexp(v2) + fexp(v3);
        }
        atomicAdd(&rsum[r0l], rp0);
        atomicAdd(&rsum[r1l], rp1);
    }
    __syncthreads();
    if (tid < 128) atomicAdd(&g_rowsum[m0 + tid], rsum[tid]);
}

// ---------------- persistent recurrence kernel (pipelined, relaxed) ----------
// blocks 0-95: LSTM. partial gates (k,hx) overlap with attention(t-1); only
// the a-part + cell are on the serial chain. blocks 96-127: attention.
// hx double-buffered by step parity. c1: 96 posts/step, c2: 32 posts/step.
__global__ __launch_bounds__(256) void k_recur(
    const float* __restrict__ W_ih, const float* __restrict__ W_hh,
    const float* __restrict__ b_ih, const float* __restrict__ b_hh,
    const int* __restrict__ entlens)
{
    extern __shared__ float sx[];
    float* sa  = sx;               // 8*512
    float* sk  = sx + 4096;        // 8*512
    float* sh  = sx + 8192;        // 8*512
    float* gsh = sx + 12288;       // 192
    __shared__ float cxs[48];
    __shared__ float sc[NEN];

    int tid = threadIdx.x;
    int blk = blockIdx.x;
    int warp = tid >> 5, lane = tid & 31;
    bool isAtt = (blk >= 96);

    int ng = 0, g0 = 0;
    const float4 *wa0=nullptr,*wa1=nullptr,*wa2=nullptr,*wb0=nullptr,*wb1=nullptr,*wb2=nullptr;
    float bias0=0.f, bias1=0.f, bias2=0.f;
    bool has2 = false;
    int ab = 0, ah = 0, alen = 0;

    if (!isAtt) {
        ng = (blk < 32) ? 6 : 5;
        g0 = (blk < 32) ? blk*6 : 192 + (blk - 32)*5;
        int nrows = 4*ng;
        int lr0 = warp, lr1 = warp + 8, lr2 = warp + 16;
        has2 = (lr2 < nrows);
        int r0 = (lr0 & 3)*512 + g0 + (lr0 >> 2);
        int r1 = (lr1 & 3)*512 + g0 + (lr1 >> 2);
        int r2 = has2 ? ((lr2 & 3)*512 + g0 + (lr2 >> 2)) : r0;
        wa0 = (const float4*)(W_ih + (size_t)r0*1024);
        wa1 = (const float4*)(W_ih + (size_t)r1*1024);
        wa2 = (const float4*)(W_ih + (size_t)r2*1024);
        wb0 = (const float4*)(W_hh + (size_t)r0*512);
        wb1 = (const float4*)(W_hh + (size_t)r1*512);
        wb2 = (const float4*)(W_hh + (size_t)r2*512);
        bias0 = b_ih[r0] + b_hh[r0];
        bias1 = b_ih[r1] + b_hh[r1];
        bias2 = has2 ? (b_ih[r2] + b_hh[r2]) : 0.f;
        if (tid < ng*8)
            cxs[tid] = g_cx[(tid & 7)*HH + g0 + (tid >> 3)];
    } else {
        ab = (blk - 96) >> 2;
        ah = (blk - 96) & 3;
        alen = __ldg(&entlens[ab]);
    }

    if (!isAtt) {
        for (int t = 0; t < TT; t++) {
            // wait: all hx(t-1) written (own post from end of t-1 included)
            if (t) {
                if (tid == 0) { unsigned tgt = 96u*t; while (ld_poll(&g_c1) < tgt) {} }
                __syncthreads();
            }
            const float* hxin = g_hx2 + ((t+1)&1)*(BB*HH);
            for (int i = tid; i < 1024; i += 256) {
                int b = i >> 7, j = i & 127;
                ((float4*)sh)[i] = ldcg4(hxin + (size_t)b*HH + j*4);
                ((float4*)sk)[i] = ldcg4(g_kseq + (size_t)((b)*TT + t)*HH + j*4);
            }
            __syncthreads();

            float acc0[8], acc1[8], acc2[8];
            #pragma unroll
            for (int b = 0; b < 8; b++) { acc0[b] = 0.f; acc1[b] = 0.f; acc2[b] = 0.f; }

            // partial: k part (W_ih cols 512..1023)
            #pragma unroll
            for (int i = 0; i < 4; i++) {
                float4 w0 = wa0[128 + i*32 + lane];
                float4 w1 = wa1[128 + i*32 + lane];
                float4 w2 = wa2[128 + i*32 + lane];
                #pragma unroll
                for (int b = 0; b < 8; b++) {
                    float4 x = *(const float4*)&sk[b*512 + ((i*32 + lane) << 2)];
                    acc0[b] = fmaf(w0.x,x.x, fmaf(w0.y,x.y, fmaf(w0.z,x.z, fmaf(w0.w,x.w, acc0[b]))));
                    acc1[b] = fmaf(w1.x,x.x, fmaf(w1.y,x.y, fmaf(w1.z,x.z, fmaf(w1.w,x.w, acc1[b]))));
                    acc2[b] = fmaf(w2.x,x.x, fmaf(w2.y,x.y, fmaf(w2.z,x.z, fmaf(w2.w,x.w, acc2[b]))));
                }
            }
            // partial: hx part (W_hh)
            #pragma unroll
            for (int i = 0; i < 4; i++) {
                float4 w0 = wb0[i*32 + lane];
                float4 w1 = wb1[i*32 + lane];
                float4 w2 = wb2[i*32 + lane];
                #pragma unroll
                for (int b = 0; b < 8; b++) {
                    float4 x = *(const float4*)&sh[b*512 + ((i*32 + lane) << 2)];
                    acc0[b] = fmaf(w0.x,x.x, fmaf(w0.y,x.y, fmaf(w0.z,x.z, fmaf(w0.w,x.w, acc0[b]))));
                    acc1[b] = fmaf(w1.x,x.x, fmaf(w1.y,x.y, fmaf(w1.z,x.z, fmaf(w1.w,x.w, acc1[b]))));
                    acc2[b] = fmaf(w2.x,x.x, fmaf(w2.y,x.y, fmaf(w2.z,x.z, fmaf(w2.w,x.w, acc2[b]))));
                }
            }

            // wait: a(t-1) ready
            if (t) {
                if (tid == 0) { unsigned tgt = 32u*t; while (ld_poll(&g_c2) < tgt) {} }
            }
            __syncthreads();
            for (int i = tid; i < 1024; i += 256) {
                int b = i >> 7, j = i & 127;
                ((float4*)sa)[i] = ldcg4(g_a + (size_t)b*HH + j*4);
            }
            __syncthreads();

            // final: a part (W_ih cols 0..511)
            #pragma unroll
            for (int i = 0; i < 4; i++) {
                float4 w0 = wa0[i*32 + lane];
                float4 w1 = wa1[i*32 + lane];
                float4 w2 = wa2[i*32 + lane];
                #pragma unroll
                for (int b = 0; b < 8; b++) {
                    float4 x = *(const float4*)&sa[b*512 + ((i*32 + lane) << 2)];
                    acc0[b] = fmaf(w0.x,x.x, fmaf(w0.y,x.y, fmaf(w0.z,x.z, fmaf(w0.w,x.w, acc0[b]))));
                    acc1[b] = fmaf(w1.x,x.x, fmaf(w1.y,x.y, fmaf(w1.z,x.z, fmaf(w1.w,x.w, acc1[b]))));
                    acc2[b] = fmaf(w2.x,x.x, fmaf(w2.y,x.y, fmaf(w2.z,x.z, fmaf(w2.w,x.w, acc2[b]))));
                }
            }
            #pragma unroll
            for (int b = 0; b < 8; b++) {
                float v0 = acc0[b], v1 = acc1[b], v2 = acc2[b];
                #pragma unroll
                for (int o = 16; o; o >>= 1) {
                    v0 += __shfl_xor_sync(0xffffffffu, v0, o);
                    v1 += __shfl_xor_sync(0xffffffffu, v1, o);
                    v2 += __shfl_xor_sync(0xffffffffu, v2, o);
                }
                if (lane == 0) {
                    gsh[warp*8 + b]     = v0 + bias0;
                    gsh[(warp+8)*8 + b] = v1 + bias1;
                    if (has2) gsh[(warp+16)*8 + b] = v2 + bias2;
                }
            }
            __syncthreads();
            float hxv = 0.f; int hb = 0, hh = 0;
            if (tid < ng*8) {
                int lg = tid >> 3; hb = tid & 7;
                hh = g0 + lg;
                float gi = gsh[(lg*4 + 0)*8 + hb];
                float gf = gsh[(lg*4 + 1)*8 + hb];
                float gg = gsh[(lg*4 + 2)*8 + hb];
                float go = gsh[(lg*4 + 3)*8 + hb];
                float c  = sigf(gf)*cxs[tid] + sigf(gi)*tanhf(gg);
                hxv = sigf(go)*tanhf(c);
                cxs[tid] = c;
                g_hx2[(t&1)*(BB*HH) + hb*HH + hh] = hxv;
            }
            __syncthreads();
            if (tid == 0) red_add(&g_c1);
            // non-critical l writes after the post
            if (tid < ng*8) {
                size_t li = ((size_t)(hb*TT + t))*1024 + hh;
                g_l[li]  = hxv;
                g_lb[li] = __float2bfloat16(hxv);
            }
        }
    } else {
        float* hxs = sh;
        for (int t = 0; t < TT; t++) {
            if (tid == 0) { unsigned tgt = 96u*(t+1); while (ld_poll(&g_c1) < tgt) {} }
            __syncthreads();

            const float* hxin = g_hx2 + (t&1)*(BB*HH) + (size_t)ab*HH;
            for (int i = tid; i < 128; i += 256)
                ((float4*)hxs)[i] = ldcg4(hxin + i*4);
            __syncthreads();

            {   // scores: 64 n x 4 threads (P slice L1-resident)
                int n = tid >> 2, sub = tid & 3;
                const float4* p4 = (const float4*)(g_P + ((size_t)(ah*512 + ab*64 + n))*512 + sub*128);
                const float4* x4 = (const float4*)(hxs + sub*128);
                float acc = 0.f;
                #pragma unroll 8
                for (int i = 0; i < 32; i++) {
                    float4 p = __ldg(&p4[i]), x = x4[i];
                    acc = fmaf(p.x,x.x, fmaf(p.y,x.y, fmaf(p.z,x.z, fmaf(p.w,x.w, acc))));
                }
                acc += __shfl_xor_sync(0xffffffffu, acc, 1);
                acc += __shfl_xor_sync(0xffffffffu, acc, 2);
                if (sub == 0)
                    sc[n] = (n <= alen) ? acc * 0.04419417382415922f : -1e30f;
            }
            __syncthreads();
            if (tid < 32) {
                float v0 = sc[tid], v1 = sc[tid + 32];
                float m = fmaxf(v0, v1);
                #pragma unroll
                for (int o = 16; o; o >>= 1) m = fmaxf(m, __shfl_xor_sync(0xffffffffu, m, o));
                float e0 = __expf(v0 - m), e1 = __expf(v1 - m);
                float s2 = e0 + e1;
                #pragma unroll
                for (int o = 16; o; o >>= 1) s2 += __shfl_xor_sync(0xffffffffu, s2, o);
                float inv = 1.0f / s2;
                sc[tid]      = e0 * inv;
                sc[tid + 32] = e1 * inv;
            }
            __syncthreads();
            float av = 0.f; int hv = 0; bool wr = false;
            {   // a = attn . V (V slice L1-resident)
                int d = tid >> 1, half = tid & 1;
                const float* vb = g_V + ((size_t)(ab*64 + half*32))*512 + ah*128 + d;
                float acc = 0.f;
                #pragma unroll 8
                for (int n2 = 0; n2 < 32; n2++)
                    acc = fmaf(sc[half*32 + n2], __ldg(&vb[(size_t)n2*512]), acc);
                float other = __shfl_xor_sync(0xffffffffu, acc, 1);
                if (half == 0) {
                    av = acc + other;
                    hv = ah*128 + d;
                    wr = true;
                    g_a[ab*HH + hv] = av;
                }
            }
            __syncthreads();
            if (tid == 0) red_add(&g_c2);
            if (wr) {
                size_t li = ((size_t)(ab*TT + t))*1024 + 512 + hv;
                g_l[li]  = av;
                g_lb[li] = __float2bfloat16(av);
            }
        }
    }
}

__global__ __launch_bounds__(256) void k_switch(
    const float* __restrict__ sw_W, const float* __restrict__ sw_b)
{
    int r = blockIdx.x*8 + (threadIdx.x >> 5);
    int lane = threadIdx.x & 31;
    const float4* l4 = (const float4*)(g_l + (size_t)r*1024);
    const float4* w4 = (const float4*)sw_W;
    float acc = 0.f;
    #pragma unroll
    for (int i = 0; i < 8; i++) {
        float4 a = l4[i*32 + lane], w = w4[i*32 + lane];
        acc = fmaf(a.x,w.x, fmaf(a.y,w.y, fmaf(a.z,w.z, fmaf(a.w,w.w, acc))));
    }
    #pragma unroll
    for (int o = 16; o; o >>= 1) acc += __shfl_xor_sync(0xffffffffu, acc, o);
    if (lane == 0) g_s[r] = sigf(acc + sw_b[0]);
}

__global__ __launch_bounds__(64) void k_ptr(
    const float* __restrict__ ents, const int* __restrict__ entlens,
    float* __restrict__ out, int write_tail)
{
    __shared__ float ds[HH];
    __shared__ float red[2];
    int r = blockIdx.x;
    int b = r >> 8;
    int tid = threadIdx.x;
    for (int i = tid; i < HH; i += 64) ds[i] = g_dec[(size_t)r*HH + i];
    __syncthreads();
    int len = entlens[b];
    float sv = -1e30f;
    if (tid <= len) {
        float acc = 0.f;
        const float4* e4 = (const float4*)(ents + (size_t)(b*NEN + tid)*HH);
        const float4* d4 = (const float4*)ds;
        #pragma unroll 8
        for (int i = 0; i < HH/4; i++) {
            float4 ev = e4[i], dv = d4[i];
            acc = fmaf(ev.x,dv.x, fmaf(ev.y,dv.y, fmaf(ev.z,dv.z, fmaf(ev.w,dv.w, acc))));
        }
        sv = acc;
    }
    float v = sv;
    #pragma unroll
    for (int o = 16; o; o >>= 1) v = fmaxf(v, __shfl_xor_sync(0xffffffffu, v, o));
    if ((tid & 31) == 0) red[tid >> 5] = v;
    __syncthreads();
    float m = fmaxf(red[0], red[1]);
    float e = (tid <= len) ? __expf(sv - m) : 0.f;
    float s2 = e;
    #pragma unroll
    for (int o = 16; o; o >>= 1) s2 += __shfl_xor_sync(0xffffffffu, s2, o);
    if ((tid & 31) == 0) red[tid >> 5] = s2;
    __syncthreads();
    float inv = 1.0f / (red[0] + red[1]);
    float s = g_s[r];
    float z = e * inv * (1.0f - s);
    out[(size_t)r*LDO + VOCAB + tid] = flog(z + 1e-6f);
    if (write_tail) out[(size_t)NROWS*LDO + (size_t)r*NEN + tid] = z;
}

__global__ void k_rowc() {
    int r = blockIdx.x*256 + threadIdx.x;
    if (r < NROWS) g_c[r] = g_s[r] / g_rowsum[r];
}

__global__ __launch_bounds__(256) void k_final(float* __restrict__ out) {
    int r = blockIdx.x;
    float c = g_c[r];
    const __nv_bfloat162* src = (const __nv_bfloat162*)(g_logb + (size_t)r*VOCAB);
    float* dst = out + (size_t)r*LDO;
    for (int i = threadIdx.x; i < VOCAB/2; i += 256) {
        __nv_bfloat162 p = src[i];
        float2 o;
        o.x = flog(fmaf(fexp(__bfloat162float(p.x)), c, 1e-6f));
        o.y = flog(fmaf(fexp(__bfloat162float(p.y)), c, 1e-6f));
        *(float2*)&dst[i*2] = o;
    }
}

extern "C" void kernel_launch(void* const* d_in, const int* in_sizes, int n_in,
                              void* d_out, int out_size)
{
    const int*   outp    = (const int*)  d_in[0];
    const float* ents    = (const float*)d_in[1];
    const int*   entlens = (const int*)  d_in[2];
    const float* emb     = (const float*)d_in[3];
    const float* W_ih    = (const float*)d_in[4];
    const float* W_hh    = (const float*)d_in[5];
    const float* b_ih    = (const float*)d_in[6];
    const float* b_hh    = (const float*)d_in[7];
    const float* Wq      = (const float*)d_in[8];
    const float* Wk      = (const float*)d_in[9];
    const float* Wv      = (const float*)d_in[10];
    const float* out_W   = (const float*)d_in[11];
    const float* out_b   = (const float*)d_in[12];
    const float* sw_W    = (const float*)d_in[13];
    const float* sw_b    = (const float*)d_in[14];
    const float* mattn_W = (const float*)d_in[15];
    const float* mattn_b = (const float*)d_in[16];
    float* out = (float*)d_out;

    static int smem_set = 0;
    if (!smem_set) {
        cudaFuncSetAttribute(k_recur, cudaFuncAttributeMaxDynamicSharedMemorySize, 64*1024);
        smem_set = 1;
    }
    const int recur_smem = (3*4096 + 192) * 4;

    float *g_K_p, *g_V_p, *g_P_p, *g_Wqt_p, *g_l_p, *g_dec_p;
    cudaGetSymbolAddress((void**)&g_K_p, g_K);
    cudaGetSymbolAddress((void**)&g_V_p, g_V);
    cudaGetSymbolAddress((void**)&g_P_p, g_P);
    cudaGetSymbolAddress((void**)&g_Wqt_p, g_Wqt);
    cudaGetSymbolAddress((void**)&g_l_p, g_l);
    cudaGetSymbolAddress((void**)&g_dec_p, g_dec);

    k_init<<<12, 512>>>(ents);
    k_gather<<<NROWS, 128>>>(emb, outp);
    k_cvtw<<<VOCAB*1024/(256*4), 256>>>(out_W);
    k_transp<<<dim3(16,16), dim3(32,8)>>>(Wq);
    k_sgemm<<<dim3(4,4,1), 256>>>(ents, 512, 0, Wk, 512, 0, nullptr, g_K_p, 512, 0, 512);
    k_sgemm<<<dim3(4,4,1), 256>>>(ents, 512, 0, Wv, 512, 0, nullptr, g_V_p, 512, 0, 512);
    k_sgemm<<<dim3(4,4,4), 256>>>(g_K_p, 512, 128, g_Wqt_p, 512, 128, nullptr,
                                  g_P_p, 512, 512*512, 128);

    k_recur<<<GRIDN, 256, recur_smem>>>(W_ih, W_hh, b_ih, b_hh, entlens);

    k_switch<<<NROWS/8, 256>>>(sw_W, sw_b);
    k_sgemm<<<dim3(4,16,1), 256>>>(g_l_p, 1024, 0, mattn_W, 1024, 0, mattn_b,
                                   g_dec_p, 512, 0, 1024);
    k_logits_mma<<<dim3(VOCAB/128, NROWS/128), 256>>>(out_b);
    k_rowc<<<8, 256>>>();
    int write_tail = (out_size >= NROWS*LDO + NROWS*NEN) ? 1 : 0;
    k_ptr<<<NROWS, 64>>>(ents, entlens, out, write_tail);
    k_final<<<NROWS, 256>>>(out);
}

// round 10
// speedup vs baseline: 1.5795x; 1.0405x over previous
#include <cuda_runtime.h>
#include <cuda_bf16.h>
#include <cstdint>
#include <cstddef>

#define BB     8
#define TT     256
#define NEN    64
#define HH     512
#define HD     128
#define VOCAB  32000
#define NROWS  (BB*TT)
#define LDO    (VOCAB+NEN)
#define GRIDN  128

__device__ float g_KV[2*BB*NEN*HH];       // K then V
__device__ float g_P[4*512*HH];           // P[h][(b*64+n)][j]
__device__ float g_Wqt[HH*HH];
__device__ float g_kseq[(size_t)NROWS*HH];
__device__ float g_hx2[2*BB*HH];          // double-buffered hx: buf = t&1
__device__ float g_cx[BB*HH];
__device__ float g_a[BB*HH];
__device__ float g_l[(size_t)NROWS*2*HH];
__device__ float g_dec[(size_t)NROWS*HH];
__device__ float g_s[NROWS];
__device__ float g_rowsum[NROWS];
__device__ float g_c[NROWS];
__device__ unsigned g_c1, g_c2;
__device__ __nv_bfloat16 g_Wb[(size_t)VOCAB*1024];
__device__ __nv_bfloat16 g_lb[(size_t)NROWS*1024];
__device__ __nv_bfloat16 g_logb[(size_t)NROWS*VOCAB];

__device__ __forceinline__ float sigf(float x) { return 1.0f / (1.0f + __expf(-x)); }

__device__ __forceinline__ float fexp(float x) {
    float z = x * 1.44269504088896f;
    float r = z + 12582912.0f;
    int   n = __float_as_int(r) - 0x4B400000;
    float f = z - (r - 12582912.0f);
    float p = 1.33336498e-3f;
    p = fmaf(p, f, 9.61011474e-3f);
    p = fmaf(p, f, 5.55036190e-2f);
    p = fmaf(p, f, 2.40226337e-1f);
    p = fmaf(p, f, 6.93147182e-1f);
    p = fmaf(p, f, 1.0f);
    return p * __int_as_float((n + 127) << 23);
}

__device__ __forceinline__ float flog(float x) {
    int xi = __float_as_int(x);
    int e = (xi >> 23) - 127;
    float m = __int_as_float((xi & 0x7FFFFF) | 0x3F800000);
    if (m > 1.41421356f) { m *= 0.5f; e++; }
    float f = m - 1.0f;
    float p = -0.125f;
    p = fmaf(p, f,  0.14285714f);
    p = fmaf(p, f, -0.16666667f);
    p = fmaf(p, f,  0.2f);
    p = fmaf(p, f, -0.25f);
    p = fmaf(p, f,  0.33333333f);
    p = fmaf(p, f, -0.5f);
    p = fmaf(p, f,  1.0f);
    p *= f;
    return fmaf((float)e, 0.69314718056f, p);
}

__device__ __forceinline__ void red_add(unsigned* p) {
    asm volatile("red.release.gpu.global.add.u32 [%0], 1;" :: "l"(p) : "memory");
}
__device__ __forceinline__ unsigned ld_poll(unsigned* p) {
    unsigned v;
    asm volatile("ld.relaxed.gpu.global.u32 %0, [%1];" : "=r"(v) : "l"(p) : "memory");
    return v;
}
__device__ __forceinline__ float4 ldcg4(const float* p) {
    float4 v;
    asm volatile("ld.global.cg.v4.f32 {%0,%1,%2,%3}, [%4];"
                 : "=f"(v.x), "=f"(v.y), "=f"(v.z), "=f"(v.w) : "l"(p));
    return v;
}
// packed f32x2 helpers (FFMA2 path — PTX-only)
__device__ __forceinline__ void fma2(unsigned long long& acc, unsigned long long w2, unsigned long long x2) {
    asm("fma.rn.f32x2 %0, %1, %2, %0;" : "+l"(acc) : "l"(w2), "l"(x2));
}
__device__ __forceinline__ unsigned long long pack2(float w) {
    unsigned long long d; asm("mov.b64 %0, {%1, %1};" : "=l"(d) : "f"(w)); return d;
}
__device__ __forceinline__ float2 unpack2(unsigned long long v) {
    float2 r; asm("mov.b64 {%0, %1}, %2;" : "=f"(r.x), "=f"(r.y) : "l"(v)); return r;
}

// merged init + emb gather (so k_recur is the 6th launch → ncu captures it)
__global__ void k_init(const float* __restrict__ ents,
                       const float* __restrict__ emb, const int* __restrict__ outp)
{
    int blk = blockIdx.x;
    if (blk < NROWS) {
        if (threadIdx.x < 128) {
            int tok = __ldg(&outp[blk]);
            const float4* src = (const float4*)(emb + (size_t)tok*HH);
            float4* dst = (float4*)(g_kseq + (size_t)blk*HH);
            dst[threadIdx.x] = __ldg(&src[threadIdx.x]);
        }
        return;
    }
    int b2 = blk - NROWS;
    if (b2 == 0 && threadIdx.x == 0) { g_c1 = 0u; g_c2 = 0u; }
    if (b2 < BB) {
        int b = b2, h = threadIdx.x;
        float s = 0.f;
        #pragma unroll 8
        for (int n = 0; n < NEN; n++) s += ents[(size_t)(b*NEN + n)*HH + h];
        s *= (1.0f / NEN);
        g_hx2[BB*HH + b*HH + h] = s;   // parity-1 buffer = hx(-1)
        g_cx[b*HH + h] = s;
        g_a [b*HH + h] = 0.f;
    } else {
        int i = (b2 - BB)*512 + threadIdx.x;
        if (i < NROWS) g_rowsum[i] = 0.f;
    }
}

__global__ __launch_bounds__(256) void k_cvtw(const float* __restrict__ W) {
    size_t i = ((size_t)blockIdx.x*256 + threadIdx.x)*4;
    float4 v = *(const float4*)&W[i];
    __nv_bfloat162 p0 = __nv_bfloat162(__float2bfloat16(v.x), __float2bfloat16(v.y));
    __nv_bfloat162 p1 = __nv_bfloat162(__float2bfloat16(v.z), __float2bfloat16(v.w));
    *(__nv_bfloat162*)&g_Wb[i]   = p0;
    *(__nv_bfloat162*)&g_Wb[i+2] = p1;
}

__global__ void k_transp(const float* __restrict__ Wq) {
    __shared__ float t[32][33];
    int bx = blockIdx.x*32, by = blockIdx.y*32;
    int x = threadIdx.x, y = threadIdx.y;
    #pragma unroll
    for (int i = 0; i < 32; i += 8)
        t[y+i][x] = Wq[(size_t)(by + y + i)*HH + bx + x];
    __syncthreads();
    #pragma unroll
    for (int i = 0; i < 32; i += 8)
        g_Wqt[(size_t)(bx + y + i)*HH + by + x] = t[x][y+i];
}

// fp32 SGEMM: C = A@B^T + bias. useB2: z picks Bm/Bm2; else Bb = Bm + z*zB.
__global__ __launch_bounds__(256) void k_sgemm(
    const float* __restrict__ A, int lda, int zA,
    const float* __restrict__ Bm, const float* __restrict__ Bm2, int ldb, int zB, int useB2,
    const float* __restrict__ bias, float* __restrict__ C, int ldc, int zC,
    int Kdim)
{
    __shared__ float As[16][128];
    __shared__ float Bs[16][128];
    const float* Ab = A + (size_t)blockIdx.z*zA;
    const float* Bb = useB2 ? (blockIdx.z ? Bm2 : Bm) : (Bm + (size_t)blockIdx.z*zB);
    float* Cb = C + (size_t)blockIdx.z*zC;
    int m0 = blockIdx.y * 128, n0 = blockIdx.x * 128;
    int tid = threadIdx.x;
    int tx = tid & 15, ty = tid >> 4;
    int lr = tid >> 2, lc = tid & 3;
    float acc[8][8];
    #pragma unroll
    for (int i = 0; i < 8; i++)
        #pragma unroll
        for (int j = 0; j < 8; j++) acc[i][j] = 0.f;

    for (int k0 = 0; k0 < Kdim; k0 += 16) {
        #pragma unroll
        for (int i = 0; i < 2; i++) {
            float4 a4 = *(const float4*)&Ab[(size_t)(m0 + lr + 64*i)*lda + k0 + lc*4];
            As[lc*4+0][lr+64*i] = a4.x; As[lc*4+1][lr+64*i] = a4.y;
            As[lc*4+2][lr+64*i] = a4.z; As[lc*4+3][lr+64*i] = a4.w;
            float4 b4 = *(const float4*)&Bb[(size_t)(n0 + lr + 64*i)*ldb + k0 + lc*4];
            Bs[lc*4+0][lr+64*i] = b4.x; Bs[lc*4+1][lr+64*i] = b4.y;
            Bs[lc*4+2][lr+64*i] = b4.z; Bs[lc*4+3][lr+64*i] = b4.w;
        }
        __syncthreads();
        #pragma unroll
        for (int kk = 0; kk < 16; kk++) {
            float a[8], b[8];
            *(float4*)&a[0] = *(const float4*)&As[kk][ty*8];
            *(float4*)&a[4] = *(const float4*)&As[kk][ty*8+4];
            *(float4*)&b[0] = *(const float4*)&Bs[kk][tx*8];
            *(float4*)&b[4] = *(const float4*)&Bs[kk][tx*8+4];
            #pragma unroll
            for (int i = 0; i < 8; i++)
                #pragma unroll
                for (int j = 0; j < 8; j++)
                    acc[i][j] = fmaf(a[i], b[j], acc[i][j]);
        }
        __syncthreads();
    }
    #pragma unroll
    for (int i = 0; i < 8; i++) {
        int m = m0 + ty*8 + i;
        #pragma unroll
        for (int jv = 0; jv < 2; jv++) {
            int n = n0 + tx*8 + jv*4;
            float4 v;
            v.x = acc[i][jv*4+0]; v.y = acc[i][jv*4+1];
            v.z = acc[i][jv*4+2]; v.w = acc[i][jv*4+3];
            if (bias) {
                float4 bv = *(const float4*)&bias[n];
                v.x += bv.x; v.y += bv.y; v.z += bv.z; v.w += bv.w;
            }
            *(float4*)&Cb[(size_t)m*ldc + n] = v;
        }
    }
}

// ---------------- bf16 tensor-core logits GEMM + fused exp-rowsum ------------
#define PADK 40

__device__ __forceinline__ void ldsm4(uint32_t& r0, uint32_t& r1, uint32_t& r2, uint32_t& r3, uint32_t addr) {
    asm volatile("ldmatrix.sync.aligned.m8n8.x4.shared.b16 {%0,%1,%2,%3}, [%4];"
                 : "=r"(r0), "=r"(r1), "=r"(r2), "=r"(r3) : "r"(addr));
}
__device__ __forceinline__ void mma16816(float* c, const uint32_t* a, const uint32_t* b) {
    asm volatile("mma.sync.aligned.m16n8k16.row.col.f32.bf16.bf16.f32 "
                 "{%0,%1,%2,%3}, {%4,%5,%6,%7}, {%8,%9}, {%0,%1,%2,%3};"
                 : "+f"(c[0]), "+f"(c[1]), "+f"(c[2]), "+f"(c[3])
                 : "r"(a[0]), "r"(a[1]), "r"(a[2]), "r"(a[3]), "r"(b[0]), "r"(b[1]));
}

__global__ __launch_bounds__(256) void k_logits_mma(const float* __restrict__ bias)
{
    __shared__ __nv_bfloat16 As[2][128*PADK];
    __shared__ __nv_bfloat16 Bs[2][128*PADK];
    __shared__ float rsum[128];
    const int Kd = 1024;
    const __nv_bfloat16* A = g_lb;
    const __nv_bfloat16* B = g_Wb;
    int m0 = blockIdx.y*128, n0 = blockIdx.x*128;
    int tid = threadIdx.x;
    int warp = tid >> 5, lane = tid & 31;
    int wm = warp >> 2, wn = warp & 3;

    int srow = tid & 127;
    int shalf = tid >> 7;
    const __nv_bfloat16* gA = A + (size_t)(m0 + srow)*Kd + shalf*16;
    const __nv_bfloat16* gB = B + (size_t)(n0 + srow)*Kd + shalf*16;
    uint32_t sA0 = (uint32_t)__cvta_generic_to_shared(&As[0][srow*PADK + shalf*16]);
    uint32_t sB0 = (uint32_t)__cvta_generic_to_shared(&Bs[0][srow*PADK + shalf*16]);
    const uint32_t bufstrideA = (uint32_t)((char*)&As[1][0] - (char*)&As[0][0]);
    const uint32_t bufstrideB = (uint32_t)((char*)&Bs[1][0] - (char*)&Bs[0][0]);

    float acc[4][4][4];
    #pragma unroll
    for (int i = 0; i < 4; i++)
        #pragma unroll
        for (int j = 0; j < 4; j++)
            #pragma unroll
            for (int k = 0; k < 4; k++) acc[i][j][k] = 0.f;

    int aq = lane >> 3;
    int arow_off = ((aq & 1) << 3) + (lane & 7);
    int acol_off = (aq >> 1) << 3;
    int brow_off = ((aq >> 1) << 3) + (lane & 7);
    int bcol_off = (aq & 1) << 3;

    #pragma unroll
    for (int s = 0; s < 2; s++) {
        asm volatile("cp.async.cg.shared.global [%0], [%1], 16;" ::
                     "r"(sA0 + s*16), "l"(gA + s*8));
        asm volatile("cp.async.cg.shared.global [%0], [%1], 16;" ::
                     "r"(sB0 + s*16), "l"(gB + s*8));
    }
    asm volatile("cp.async.commit_group;");

    const int NIT = Kd/32;
    for (int it = 0; it < NIT; it++) {
        int buf = it & 1;
        if (it + 1 < NIT) {
            uint32_t sa = sA0 + ((it+1)&1)*bufstrideA;
            uint32_t sb = sB0 + ((it+1)&1)*bufstrideB;
            const __nv_bfloat16* ga = gA + (it+1)*32;
            const __nv_bfloat16* gb = gB + (it+1)*32;
            #pragma unroll
            for (int s = 0; s < 2; s++) {
                asm volatile("cp.async.cg.shared.global [%0], [%1], 16;" ::
                             "r"(sa + s*16), "l"(ga + s*8));
                asm volatile("cp.async.cg.shared.global [%0], [%1], 16;" ::
                             "r"(sb + s*16), "l"(gb + s*8));
            }
            asm volatile("cp.async.commit_group;");
            asm volatile("cp.async.wait_group 1;");
        } else {
            asm volatile("cp.async.wait_group 0;");
        }
        __syncthreads();

        #pragma unroll
        for (int kk = 0; kk < 2; kk++) {
            uint32_t aF[4][4], bF[4][2];
            #pragma unroll
            for (int mi = 0; mi < 4; mi++) {
                int row = wm*64 + mi*16 + arow_off;
                int col = kk*16 + acol_off;
                uint32_t ad = (uint32_t)__cvta_generic_to_shared(&As[buf][row*PADK + col]);
                ldsm4(aF[mi][0], aF[mi][1], aF[mi][2], aF[mi][3], ad);
            }
            #pragma unroll
            for (int np = 0; np < 2; np++) {
                int row = wn*32 + np*16 + brow_off;
                int col = kk*16 + bcol_off;
                uint32_t bd = (uint32_t)__cvta_generic_to_shared(&Bs[buf][row*PADK + col]);
                ldsm4(bF[np*2][0], bF[np*2][1], bF[np*2+1][0], bF[np*2+1][1], bd);
            }
            #pragma unroll
            for (int mi = 0; mi < 4; mi++)
                #pragma unroll
                for (int ni = 0; ni < 4; ni++)
                    mma16816(acc[mi][ni], aF[mi], bF[ni]);
        }
        __syncthreads();
    }

    if (tid < 128) rsum[tid] = 0.f;
    __syncthreads();

    int g = lane >> 2, tg = lane & 3;
    #pragma unroll
    for (int mi = 0; mi < 4; mi++) {
        int r0l = wm*64 + mi*16 + g;
        int r1l = r0l + 8;
        float rp0 = 0.f, rp1 = 0.f;
        #pragma unroll
        for (int ni = 0; ni < 4; ni++) {
            int n = n0 + wn*32 + ni*8 + tg*2;
            float2 bv = *(const float2*)&bias[n];
            float v0 = acc[mi][ni][0] + bv.x;
            float v1 = acc[mi][ni][1] + bv.y;
            float v2 = acc[mi][ni][2] + bv.x;
            float v3 = acc[mi][ni][3] + bv.y;
            *(__nv_bfloat162*)&g_logb[(size_t)(m0 + r0l)*VOCAB + n] =
                __nv_bfloat162(__float2bfloat16(v0), __float2bfloat16(v1));
            *(__nv_bfloat162*)&g_logb[(size_t)(m0 + r1l)*VOCAB + n] =
                __nv_bfloat162(__float2bfloat16(v2), __float2bfloat16(v3));
            rp0 += fexp(v0) + fexp(v1);
            rp1 += fexp(v2) + fexp(v3);
        }
        atomicAdd(&rsum[r0l], rp0);
        atomicAdd(&rsum[r1l], rp1);
    }
    __syncthreads();
    if (tid < 128) atomicAdd(&g_rowsum[m0 + tid], rsum[tid]);
}

// ---------------- persistent recurrence (pipelined, f32x2 GEMV) --------------
// Activations staged batch-pair interleaved: region[p*256 + j4*2 + {0,1}]
// (float4) = (x[2p][j], x[2p+1][j], x[2p][j+1], x[2p+1][j+1]).
__global__ __launch_bounds__(256) void k_recur(
    const float* __restrict__ W_ih, const float* __restrict__ W_hh,
    const float* __restrict__ b_ih, const float* __restrict__ b_hh,
    const int* __restrict__ entlens)
{
    extern __shared__ float sx[];
    float4* sa = (float4*)sx;                // 1024 float4 (a packed)
    float4* sk = (float4*)(sx + 4096);       // k packed
    float4* sh = (float4*)(sx + 8192);       // hx packed
    float* gsh = sx + 12288;                 // 192
    __shared__ float cxs[48];
    __shared__ float sc[NEN];

    int tid = threadIdx.x;
    int blk = blockIdx.x;
    int warp = tid >> 5, lane = tid & 31;
    bool isAtt = (blk >= 96);

    int ng = 0, g0 = 0;
    const float4 *wa0=nullptr,*wa1=nullptr,*wa2=nullptr,*wb0=nullptr,*wb1=nullptr,*wb2=nullptr;
    float bias0=0.f, bias1=0.f, bias2=0.f;
    bool has2 = false;
    int ab = 0, ah = 0, alen = 0;

    if (!isAtt) {
        ng = (blk < 32) ? 6 : 5;
        g0 = (blk < 32) ? blk*6 : 192 + (blk - 32)*5;
        int nrows = 4*ng;
        int lr0 = warp, lr1 = warp + 8, lr2 = warp + 16;
        has2 = (lr2 < nrows);
        int r0 = (lr0 & 3)*512 + g0 + (lr0 >> 2);
        int r1 = (lr1 & 3)*512 + g0 + (lr1 >> 2);
        int r2 = has2 ? ((lr2 & 3)*512 + g0 + (lr2 >> 2)) : r0;
        wa0 = (const float4*)(W_ih + (size_t)r0*1024);
        wa1 = (const float4*)(W_ih + (size_t)r1*1024);
        wa2 = (const float4*)(W_ih + (size_t)r2*1024);
        wb0 = (const float4*)(W_hh + (size_t)r0*512);
        wb1 = (const float4*)(W_hh + (size_t)r1*512);
        wb2 = (const float4*)(W_hh + (size_t)r2*512);
        bias0 = b_ih[r0] + b_hh[r0];
        bias1 = b_ih[r1] + b_hh[r1];
        bias2 = has2 ? (b_ih[r2] + b_hh[r2]) : 0.f;
        if (tid < ng*8)
            cxs[tid] = g_cx[(tid & 7)*HH + g0 + (tid >> 3)];
    } else {
        ab = (blk - 96) >> 2;
        ah = (blk - 96) & 3;
        alen = __ldg(&entlens[ab]);
    }

    if (!isAtt) {
        for (int t = 0; t < TT; t++) {
            // stage k(t) packed — NO sync dependency
            for (int i = tid; i < 512; i += 256) {
                int p = i >> 7, j4 = i & 127;
                float4 va = ldcg4(g_kseq + (size_t)((2*p  )*TT + t)*HH + j4*4);
                float4 vb = ldcg4(g_kseq + (size_t)((2*p+1)*TT + t)*HH + j4*4);
                sk[p*256 + j4*2 + 0] = make_float4(va.x, vb.x, va.y, vb.y);
                sk[p*256 + j4*2 + 1] = make_float4(va.z, vb.z, va.w, vb.w);
            }
            __syncthreads();

            unsigned long long accA[4], accB[4], accC[4];
            #pragma unroll
            for (int p = 0; p < 4; p++) { accA[p] = 0ull; accB[p] = 0ull; accC[p] = 0ull; }

            // k-part (W_ih cols 512..1023) — before any waits
            #pragma unroll
            for (int i = 0; i < 4; i++) {
                float4 w0 = wa0[128 + i*32 + lane];
                float4 w1 = wa1[128 + i*32 + lane];
                float4 w2 = wa2[128 + i*32 + lane];
                unsigned long long w0x=pack2(w0.x),w0y=pack2(w0.y),w0z=pack2(w0.z),w0w=pack2(w0.w);
                unsigned long long w1x=pack2(w1.x),w1y=pack2(w1.y),w1z=pack2(w1.z),w1w=pack2(w1.w);
                unsigned long long w2x=pack2(w2.x),w2y=pack2(w2.y),w2z=pack2(w2.z),w2w=pack2(w2.w);
                #pragma unroll
                for (int p = 0; p < 4; p++) {
                    ulonglong2 x01 = *(const ulonglong2*)&sk[p*256 + (i*32+lane)*2];
                    ulonglong2 x23 = *(const ulonglong2*)&sk[p*256 + (i*32+lane)*2 + 1];
                    fma2(accA[p], w0x, x01.x); fma2(accA[p], w0y, x01.y);
                    fma2(accA[p], w0z, x23.x); fma2(accA[p], w0w, x23.y);
                    fma2(accB[p], w1x, x01.x); fma2(accB[p], w1y, x01.y);
                    fma2(accB[p], w1z, x23.x); fma2(accB[p], w1w, x23.y);
                    fma2(accC[p], w2x, x01.x); fma2(accC[p], w2y, x01.y);
                    fma2(accC[p], w2z, x23.x); fma2(accC[p], w2w, x23.y);
                }
            }

            // wait hx(t-1) complete, stage it packed
            if (t) {
                if (tid == 0) { unsigned tgt = 96u*t; while (ld_poll(&g_c1) < tgt) {} }
            }
            __syncthreads();
            const float* hxin = g_hx2 + ((t+1)&1)*(BB*HH);
            for (int i = tid; i < 512; i += 256) {
                int p = i >> 7, j4 = i & 127;
                float4 va = ldcg4(hxin + (size_t)(2*p  )*HH + j4*4);
                float4 vb = ldcg4(hxin + (size_t)(2*p+1)*HH + j4*4);
                sh[p*256 + j4*2 + 0] = make_float4(va.x, vb.x, va.y, vb.y);
                sh[p*256 + j4*2 + 1] = make_float4(va.z, vb.z, va.w, vb.w);
            }
            __syncthreads();

            // hx-part (W_hh)
            #pragma unroll
            for (int i = 0; i < 4; i++) {
                float4 w0 = wb0[i*32 + lane];
                float4 w1 = wb1[i*32 + lane];
                float4 w2 = wb2[i*32 + lane];
                unsigned long long w0x=pack2(w0.x),w0y=pack2(w0.y),w0z=pack2(w0.z),w0w=pack2(w0.w);
                unsigned long long w1x=pack2(w1.x),w1y=pack2(w1.y),w1z=pack2(w1.z),w1w=pack2(w1.w);
                unsigned long long w2x=pack2(w2.x),w2y=pack2(w2.y),w2z=pack2(w2.z),w2w=pack2(w2.w);
                #pragma unroll
                for (int p = 0; p < 4; p++) {
                    ulonglong2 x01 = *(const ulonglong2*)&sh[p*256 + (i*32+lane)*2];
                    ulonglong2 x23 = *(const ulonglong2*)&sh[p*256 + (i*32+lane)*2 + 1];
                    fma2(accA[p], w0x, x01.x); fma2(accA[p], w0y, x01.y);
                    fma2(accA[p], w0z, x23.x); fma2(accA[p], w0w, x23.y);
                    fma2(accB[p], w1x, x01.x); fma2(accB[p], w1y, x01.y);
                    fma2(accB[p], w1z, x23.x); fma2(accB[p], w1w, x23.y);
                    fma2(accC[p], w2x, x01.x); fma2(accC[p], w2y, x01.y);
                    fma2(accC[p], w2z, x23.x); fma2(accC[p], w2w, x23.y);
                }
            }

            // wait a(t-1) ready, stage packed
            if (t) {
                if (tid == 0) { unsigned tgt = 32u*t; while (ld_poll(&g_c2) < tgt) {} }
            }
            __syncthreads();
            for (int i = tid; i < 512; i += 256) {
                int p = i >> 7, j4 = i & 127;
                float4 va = ldcg4(g_a + (size_t)(2*p  )*HH + j4*4);
                float4 vb = ldcg4(g_a + (size_t)(2*p+1)*HH + j4*4);
                sa[p*256 + j4*2 + 0] = make_float4(va.x, vb.x, va.y, vb.y);
                sa[p*256 + j4*2 + 1] = make_float4(va.z, vb.z, va.w, vb.w);
            }
            __syncthreads();

            // a-part (W_ih cols 0..511)
            #pragma unroll
            for (int i = 0; i < 4; i++) {
                float4 w0 = wa0[i*32 + lane];
                float4 w1 = wa1[i*32 + lane];
                float4 w2 = wa2[i*32 + lane];
                unsigned long long w0x=pack2(w0.x),w0y=pack2(w0.y),w0z=pack2(w0.z),w0w=pack2(w0.w);
                unsigned long long w1x=pack2(w1.x),w1y=pack2(w1.y),w1z=pack2(w1.z),w1w=pack2(w1.w);
                unsigned long long w2x=pack2(w2.x),w2y=pack2(w2.y),w2z=pack2(w2.z),w2w=pack2(w2.w);
                #pragma unroll
                for (int p = 0; p < 4; p++) {
                    ulonglong2 x01 = *(const ulonglong2*)&sa[p*256 + (i*32+lane)*2];
                    ulonglong2 x23 = *(const ulonglong2*)&sa[p*256 + (i*32+lane)*2 + 1];
                    fma2(accA[p], w0x, x01.x); fma2(accA[p], w0y, x01.y);
                    fma2(accA[p], w0z, x23.x); fma2(accA[p], w0w, x23.y);
                    fma2(accB[p], w1x, x01.x); fma2(accB[p], w1y, x01.y);
                    fma2(accB[p], w1z, x23.x); fma2(accB[p], w1w, x23.y);
                    fma2(accC[p], w2x, x01.x); fma2(accC[p], w2y, x01.y);
                    fma2(accC[p], w2z, x23.x); fma2(accC[p], w2w, x23.y);
                }
            }

            float a0[8], a1[8], a2[8];
            #pragma unroll
            for (int p = 0; p < 4; p++) {
                float2 u;
                u = unpack2(accA[p]); a0[2*p] = u.x; a0[2*p+1] = u.y;
                u = unpack2(accB[p]); a1[2*p] = u.x; a1[2*p+1] = u.y;
                u = unpack2(accC[p]); a2[2*p] = u.x; a2[2*p+1] = u.y;
            }
            #pragma unroll
            for (int b = 0; b < 8; b++) {
                float v0 = a0[b], v1 = a1[b], v2 = a2[b];
                #pragma unroll
                for (int o = 16; o; o >>= 1) {
                    v0 += __shfl_xor_sync(0xffffffffu, v0, o);
                    v1 += __shfl_xor_sync(0xffffffffu, v1, o);
                    v2 += __shfl_xor_sync(0xffffffffu, v2, o);
                }
                if (lane == 0) {
                    gsh[warp*8 + b]     = v0 + bias0;
                    gsh[(warp+8)*8 + b] = v1 + bias1;
                    if (has2) gsh[(warp+16)*8 + b] = v2 + bias2;
                }
            }
            __syncthreads();
            float hxv = 0.f; int hb = 0, hh = 0;
            if (tid < ng*8) {
                int lg = tid >> 3; hb = tid & 7;
                hh = g0 + lg;
                float gi = gsh[(lg*4 + 0)*8 + hb];
                float gf = gsh[(lg*4 + 1)*8 + hb];
                float gg = gsh[(lg*4 + 2)*8 + hb];
                float go = gsh[(lg*4 + 3)*8 + hb];
                float c  = sigf(gf)*cxs[tid] + sigf(gi)*tanhf(gg);
                hxv = sigf(go)*tanhf(c);
                cxs[tid] = c;
                g_hx2[(t&1)*(BB*HH) + hb*HH + hh] = hxv;
            }
            __syncthreads();
            if (tid == 0) red_add(&g_c1);
            if (tid < ng*8) {
                size_t li = ((size_t)(hb*TT + t))*1024 + hh;
                g_l[li]  = hxv;
                g_lb[li] = __float2bfloat16(hxv);
            }
        }
    } else {
        const float* g_V = g_KV + BB*NEN*HH;
        float* hxs = (float*)sh;
        for (int t = 0; t < TT; t++) {
            if (tid == 0) { unsigned tgt = 96u*(t+1); while (ld_poll(&g_c1) < tgt) {} }
            __syncthreads();

            const float* hxin = g_hx2 + (t&1)*(BB*HH) + (size_t)ab*HH;
            for (int i = tid; i < 128; i += 256)
                ((float4*)hxs)[i] = ldcg4(hxin + i*4);
            __syncthreads();

            {   // scores: 64 n x 4 threads (P slice L1-resident)
                int n = tid >> 2, sub = tid & 3;
                const float4* p4 = (const float4*)(g_P + ((size_t)(ah*512 + ab*64 + n))*512 + sub*128);
                const float4* x4 = (const float4*)(hxs + sub*128);
                float acc = 0.f;
                #pragma unroll 8
                for (int i = 0; i < 32; i++) {
                    float4 p = __ldg(&p4[i]), x = x4[i];
                    acc = fmaf(p.x,x.x, fmaf(p.y,x.y, fmaf(p.z,x.z, fmaf(p.w,x.w, acc))));
                }
                acc += __shfl_xor_sync(0xffffffffu, acc, 1);
                acc += __shfl_xor_sync(0xffffffffu, acc, 2);
                if (sub == 0)
                    sc[n] = (n <= alen) ? acc * 0.04419417382415922f : -1e30f;
            }
            __syncthreads();
            if (tid < 32) {
                float v0 = sc[tid], v1 = sc[tid + 32];
                float m = fmaxf(v0, v1);
                #pragma unroll
                for (int o = 16; o; o >>= 1) m = fmaxf(m, __shfl_xor_sync(0xffffffffu, m, o));
                float e0 = __expf(v0 - m), e1 = __expf(v1 - m);
                float s2 = e0 + e1;
                #pragma unroll
                for (int o = 16; o; o >>= 1) s2 += __shfl_xor_sync(0xffffffffu, s2, o);
                float inv = 1.0f / s2;
                sc[tid]      = e0 * inv;
                sc[tid + 32] = e1 * inv;
            }
            __syncthreads();
            float av = 0.f; int hv = 0; bool wr = false;
            {   // a = attn . V (V slice L1-resident)
                int d = tid >> 1, half = tid & 1;
                const float* vb = g_V + ((size_t)(ab*64 + half*32))*512 + ah*128 + d;
                float acc = 0.f;
                #pragma unroll 8
                for (int n2 = 0; n2 < 32; n2++)
                    acc = fmaf(sc[half*32 + n2], __ldg(&vb[(size_t)n2*512]), acc);
                float other = __shfl_xor_sync(0xffffffffu, acc, 1);
                if (half == 0) {
                    av = acc + other;
                    hv = ah*128 + d;
                    wr = true;
                    g_a[ab*HH + hv] = av;
                }
            }
            __syncthreads();
            if (tid == 0) red_add(&g_c2);
            if (wr) {
                size_t li = ((size_t)(ab*TT + t))*1024 + 512 + hv;
                g_l[li]  = av;
                g_lb[li] = __float2bfloat16(av);
            }
        }
    }
}

__global__ __launch_bounds__(256) void k_switch(
    const float* __restrict__ sw_W, const float* __restrict__ sw_b)
{
    int r = blockIdx.x*8 + (threadIdx.x >> 5);
    int lane = threadIdx.x & 31;
    const float4* l4 = (const float4*)(g_l + (size_t)r*1024);
    const float4* w4 = (const float4*)sw_W;
    float acc = 0.f;
    #pragma unroll
    for (int i = 0; i < 8; i++) {
        float4 a = l4[i*32 + lane], w = w4[i*32 + lane];
        acc = fmaf(a.x,w.x, fmaf(a.y,w.y, fmaf(a.z,w.z, fmaf(a.w,w.w, acc))));
    }
    #pragma unroll
    for (int o = 16; o; o >>= 1) acc += __shfl_xor_sync(0xffffffffu, acc, o);
    if (lane == 0) g_s[r] = sigf(acc + sw_b[0]);
}

__global__ __launch_bounds__(64) void k_ptr(
    const float* __restrict__ ents, const int* __restrict__ entlens,
    float* __restrict__ out, int write_tail)
{
    __shared__ float ds[HH];
    __shared__ float red[2];
    int r = blockIdx.x;
    int b = r >> 8;
    int tid = threadIdx.x;
    for (int i = tid; i < HH; i += 64) ds[i] = g_dec[(size_t)r*HH + i];
    __syncthreads();
    int len = entlens[b];
    float sv = -1e30f;
    if (tid <= len) {
        float acc = 0.f;
        const float4* e4 = (const float4*)(ents + (size_t)(b*NEN + tid)*HH);
        const float4* d4 = (const float4*)ds;
        #pragma unroll 8
        for (int i = 0; i < HH/4; i++) {
            float4 ev = e4[i], dv = d4[i];
            acc = fmaf(ev.x,dv.x, fmaf(ev.y,dv.y, fmaf(ev.z,dv.z, fmaf(ev.w,dv.w, acc))));
        }
        sv = acc;
    }
    float v = sv;
    #pragma unroll
    for (int o = 16; o; o >>= 1) v = fmaxf(v, __shfl_xor_sync(0xffffffffu, v, o));
    if ((tid & 31) == 0) red[tid >> 5] = v;
    __syncthreads();
    float m = fmaxf(red[0], red[1]);
    float e = (tid <= len) ? __expf(sv - m) : 0.f;
    float s2 = e;
    #pragma unroll
    for (int o = 16; o; o >>= 1) s2 += __shfl_xor_sync(0xffffffffu, s2, o);
    if ((tid & 31) == 0) red[tid >> 5] = s2;
    __syncthreads();
    float inv = 1.0f / (red[0] + red[1]);
    float s = g_s[r];
    float z = e * inv * (1.0f - s);
    out[(size_t)r*LDO + VOCAB + tid] = flog(z + 1e-6f);
    if (write_tail) out[(size_t)NROWS*LDO + (size_t)r*NEN + tid] = z;
}

__global__ void k_rowc() {
    int r = blockIdx.x*256 + threadIdx.x;
    if (r < NROWS) g_c[r] = g_s[r] / g_rowsum[r];
}

__global__ __launch_bounds__(256) void k_final(float* __restrict__ out) {
    int r = blockIdx.x;
    float c = g_c[r];
    const __nv_bfloat162* src = (const __nv_bfloat162*)(g_logb + (size_t)r*VOCAB);
    float* dst = out + (size_t)r*LDO;
    for (int i = threadIdx.x; i < VOCAB/2; i += 256) {
        __nv_bfloat162 p = src[i];
        float2 o;
        o.x = flog(fmaf(fexp(__bfloat162float(p.x)), c, 1e-6f));
        o.y = flog(fmaf(fexp(__bfloat162float(p.y)), c, 1e-6f));
        *(float2*)&dst[i*2] = o;
    }
}

extern "C" void kernel_launch(void* const* d_in, const int* in_sizes, int n_in,
                              void* d_out, int out_size)
{
    const int*   outp    = (const int*)  d_in[0];
    const float* ents    = (const float*)d_in[1];
    const int*   entlens = (const int*)  d_in[2];
    const float* emb     = (const float*)d_in[3];
    const float* W_ih    = (const float*)d_in[4];
    const float* W_hh    = (const float*)d_in[5];
    const float* b_ih    = (const float*)d_in[6];
    const float* b_hh    = (const float*)d_in[7];
    const float* Wq      = (const float*)d_in[8];
    const float* Wk      = (const float*)d_in[9];
    const float* Wv      = (const float*)d_in[10];
    const float* out_W   = (const float*)d_in[11];
    const float* out_b   = (const float*)d_in[12];
    const float* sw_W    = (const float*)d_in[13];
    const float* sw_b    = (const float*)d_in[14];
    const float* mattn_W = (const float*)d_in[15];
    const float* mattn_b = (const float*)d_in[16];
    float* out = (float*)d_out;

    static int smem_set = 0;
    if (!smem_set) {
        cudaFuncSetAttribute(k_recur, cudaFuncAttributeMaxDynamicSharedMemorySize, 64*1024);
        smem_set = 1;
    }
    const int recur_smem = (3*4096 + 192) * 4;

    float *g_KV_p, *g_P_p, *g_Wqt_p, *g_l_p, *g_dec_p;
    cudaGetSymbolAddress((void**)&g_KV_p, g_KV);
    cudaGetSymbolAddress((void**)&g_P_p, g_P);
    cudaGetSymbolAddress((void**)&g_Wqt_p, g_Wqt);
    cudaGetSymbolAddress((void**)&g_l_p, g_l);
    cudaGetSymbolAddress((void**)&g_dec_p, g_dec);

    // launch order chosen so k_recur is the 6th launch (ncu -s 5 -c 1 captures it)
    k_init<<<NROWS + 12, 512>>>(ents, emb, outp);                       // 1
    k_cvtw<<<VOCAB*1024/(256*4), 256>>>(out_W);                         // 2
    k_transp<<<dim3(16,16), dim3(32,8)>>>(Wq);                          // 3
    k_sgemm<<<dim3(4,4,2), 256>>>(ents, 512, 0, Wk, Wv, 512, 0, 1,      // 4 (K+V)
                                  nullptr, g_KV_p, 512, BB*NEN*HH, 512);
    k_sgemm<<<dim3(4,4,4), 256>>>(g_KV_p, 512, 128, g_Wqt_p, g_Wqt_p, 512, 128, 0,  // 5 (P)
                                  nullptr, g_P_p, 512, 512*512, 128);
    k_recur<<<GRIDN, 256, recur_smem>>>(W_ih, W_hh, b_ih, b_hh, entlens); // 6 ← ncu

    k_switch<<<NROWS/8, 256>>>(sw_W, sw_b);
    k_sgemm<<<dim3(4,16,1), 256>>>(g_l_p, 1024, 0, mattn_W, mattn_W, 1024, 0, 0,
                                   mattn_b, g_dec_p, 512, 0, 1024);
    k_logits_mma<<<dim3(VOCAB/128, NROWS/128), 256>>>(out_b);
    k_rowc<<<8, 256>>>();
    int write_tail = (out_size >= NROWS*LDO + NROWS*NEN) ? 1 : 0;
    k_ptr<<<NROWS, 64>>>(ents, entlens, out, write_tail);
    k_final<<<NROWS, 256>>>(out);
}

// round 11
// speedup vs baseline: 1.5908x; 1.0071x over previous
#include <cuda_runtime.h>
#include <cuda_bf16.h>
#include <cstdint>
#include <cstddef>

#define BB     8
#define TT     256
#define NEN    64
#define HH     512
#define HD     128
#define VOCAB  32000
#define NROWS  (BB*TT)
#define LDO    (VOCAB+NEN)
#define GRIDN  128

__device__ float g_KV[2*BB*NEN*HH];       // K then V
__device__ float g_P[4*512*HH];           // P[h][(b*64+n)][j]
__device__ float g_Wqt[HH*HH];
__device__ float g_kseq[(size_t)NROWS*HH];
__device__ float g_hx2[2*BB*HH];          // double-buffered hx: buf = t&1
__device__ float g_cx[BB*HH];
__device__ float g_a[BB*HH];
__device__ float g_l[(size_t)NROWS*2*HH];
__device__ float g_dec[(size_t)NROWS*HH];
__device__ float g_s[NROWS];
__device__ float g_rowsum[NROWS];
__device__ float g_c[NROWS];
__device__ unsigned g_c1, g_c2;
__device__ __nv_bfloat16 g_Wb[(size_t)VOCAB*1024];
__device__ __nv_bfloat16 g_lb[(size_t)NROWS*1024];
__device__ __nv_bfloat16 g_logb[(size_t)NROWS*VOCAB];

__device__ __forceinline__ float sigf(float x) { return 1.0f / (1.0f + __expf(-x)); }

__device__ __forceinline__ float fexp(float x) {
    float z = x * 1.44269504088896f;
    float r = z + 12582912.0f;
    int   n = __float_as_int(r) - 0x4B400000;
    float f = z - (r - 12582912.0f);
    float p = 1.33336498e-3f;
    p = fmaf(p, f, 9.61011474e-3f);
    p = fmaf(p, f, 5.55036190e-2f);
    p = fmaf(p, f, 2.40226337e-1f);
    p = fmaf(p, f, 6.93147182e-1f);
    p = fmaf(p, f, 1.0f);
    return p * __int_as_float((n + 127) << 23);
}

__device__ __forceinline__ float flog(float x) {
    int xi = __float_as_int(x);
    int e = (xi >> 23) - 127;
    float m = __int_as_float((xi & 0x7FFFFF) | 0x3F800000);
    if (m > 1.41421356f) { m *= 0.5f; e++; }
    float f = m - 1.0f;
    float p = -0.125f;
    p = fmaf(p, f,  0.14285714f);
    p = fmaf(p, f, -0.16666667f);
    p = fmaf(p, f,  0.2f);
    p = fmaf(p, f, -0.25f);
    p = fmaf(p, f,  0.33333333f);
    p = fmaf(p, f, -0.5f);
    p = fmaf(p, f,  1.0f);
    p *= f;
    return fmaf((float)e, 0.69314718056f, p);
}

__device__ __forceinline__ void red_add(unsigned* p) {
    asm volatile("red.release.gpu.global.add.u32 [%0], 1;" :: "l"(p) : "memory");
}
__device__ __forceinline__ unsigned ld_poll(unsigned* p) {
    unsigned v;
    asm volatile("ld.relaxed.gpu.global.u32 %0, [%1];" : "=r"(v) : "l"(p) : "memory");
    return v;
}
__device__ __forceinline__ float4 ldcg4(const float* p) {
    float4 v;
    asm volatile("ld.global.cg.v4.f32 {%0,%1,%2,%3}, [%4];"
                 : "=f"(v.x), "=f"(v.y), "=f"(v.z), "=f"(v.w) : "l"(p));
    return v;
}
__device__ __forceinline__ void fma2(unsigned long long& acc, unsigned long long w2, unsigned long long x2) {
    asm("fma.rn.f32x2 %0, %1, %2, %0;" : "+l"(acc) : "l"(w2), "l"(x2));
}
__device__ __forceinline__ unsigned long long pack2(float w) {
    unsigned long long d; asm("mov.b64 %0, {%1, %1};" : "=l"(d) : "f"(w)); return d;
}
__device__ __forceinline__ float2 unpack2(unsigned long long v) {
    float2 r; asm("mov.b64 {%0, %1}, %2;" : "=f"(r.x), "=f"(r.y) : "l"(v)); return r;
}

// merged init + emb gather + Wq transpose (k_recur must be launch #4 for ncu)
__global__ void k_init(const float* __restrict__ ents,
                       const float* __restrict__ emb, const int* __restrict__ outp,
                       const float* __restrict__ Wq)
{
    int blk = blockIdx.x;
    if (blk < NROWS) {
        if (threadIdx.x < 128) {
            int tok = __ldg(&outp[blk]);
            const float4* src = (const float4*)(emb + (size_t)tok*HH);
            float4* dst = (float4*)(g_kseq + (size_t)blk*HH);
            dst[threadIdx.x] = __ldg(&src[threadIdx.x]);
        }
        return;
    }
    int b2 = blk - NROWS;
    if (b2 < 12) {
        if (b2 == 0 && threadIdx.x == 0) { g_c1 = 0u; g_c2 = 0u; }
        if (b2 < BB) {
            int b = b2, h = threadIdx.x;
            float s = 0.f;
            #pragma unroll 8
            for (int n = 0; n < NEN; n++) s += ents[(size_t)(b*NEN + n)*HH + h];
            s *= (1.0f / NEN);
            g_hx2[BB*HH + b*HH + h] = s;   // parity-1 buffer = hx(-1)
            g_cx[b*HH + h] = s;
            g_a [b*HH + h] = 0.f;
        } else {
            int i = (b2 - BB)*512 + threadIdx.x;
            if (i < NROWS) g_rowsum[i] = 0.f;
        }
        return;
    }
    // Wq transpose tiles: 256 blocks of 32x32
    __shared__ float t[32][33];
    int idx = b2 - 12;
    int bx = (idx & 15)*32, by = (idx >> 4)*32;
    int x = threadIdx.x & 31, yy = threadIdx.x >> 5;   // 512 threads: 16 rows/pass
    #pragma unroll
    for (int i = 0; i < 32; i += 16)
        t[yy+i][x] = Wq[(size_t)(by + yy + i)*HH + bx + x];
    __syncthreads();
    #pragma unroll
    for (int i = 0; i < 32; i += 16)
        g_Wqt[(size_t)(bx + yy + i)*HH + by + x] = t[x][yy+i];
}

__global__ __launch_bounds__(256) void k_cvtw(const float* __restrict__ W) {
    size_t i = ((size_t)blockIdx.x*256 + threadIdx.x)*4;
    float4 v = *(const float4*)&W[i];
    __nv_bfloat162 p0 = __nv_bfloat162(__float2bfloat16(v.x), __float2bfloat16(v.y));
    __nv_bfloat162 p1 = __nv_bfloat162(__float2bfloat16(v.z), __float2bfloat16(v.w));
    *(__nv_bfloat162*)&g_Wb[i]   = p0;
    *(__nv_bfloat162*)&g_Wb[i+2] = p1;
}

// fp32 SGEMM: C = A@B^T + bias. useB2: z picks Bm/Bm2; else Bb = Bm + z*zB.
__global__ __launch_bounds__(256) void k_sgemm(
    const float* __restrict__ A, int lda, int zA,
    const float* __restrict__ Bm, const float* __restrict__ Bm2, int ldb, int zB, int useB2,
    const float* __restrict__ bias, float* __restrict__ C, int ldc, int zC,
    int Kdim)
{
    __shared__ float As[16][128];
    __shared__ float Bs[16][128];
    const float* Ab = A + (size_t)blockIdx.z*zA;
    const float* Bb = useB2 ? (blockIdx.z ? Bm2 : Bm) : (Bm + (size_t)blockIdx.z*zB);
    float* Cb = C + (size_t)blockIdx.z*zC;
    int m0 = blockIdx.y * 128, n0 = blockIdx.x * 128;
    int tid = threadIdx.x;
    int tx = tid & 15, ty = tid >> 4;
    int lr = tid >> 2, lc = tid & 3;
    float acc[8][8];
    #pragma unroll
    for (int i = 0; i < 8; i++)
        #pragma unroll
        for (int j = 0; j < 8; j++) acc[i][j] = 0.f;

    for (int k0 = 0; k0 < Kdim; k0 += 16) {
        #pragma unroll
        for (int i = 0; i < 2; i++) {
            float4 a4 = *(const float4*)&Ab[(size_t)(m0 + lr + 64*i)*lda + k0 + lc*4];
            As[lc*4+0][lr+64*i] = a4.x; As[lc*4+1][lr+64*i] = a4.y;
            As[lc*4+2][lr+64*i] = a4.z; As[lc*4+3][lr+64*i] = a4.w;
            float4 b4 = *(const float4*)&Bb[(size_t)(n0 + lr + 64*i)*ldb + k0 + lc*4];
            Bs[lc*4+0][lr+64*i] = b4.x; Bs[lc*4+1][lr+64*i] = b4.y;
            Bs[lc*4+2][lr+64*i] = b4.z; Bs[lc*4+3][lr+64*i] = b4.w;
        }
        __syncthreads();
        #pragma unroll
        for (int kk = 0; kk < 16; kk++) {
            float a[8], b[8];
            *(float4*)&a[0] = *(const float4*)&As[kk][ty*8];
            *(float4*)&a[4] = *(const float4*)&As[kk][ty*8+4];
            *(float4*)&b[0] = *(const float4*)&Bs[kk][tx*8];
            *(float4*)&b[4] = *(const float4*)&Bs[kk][tx*8+4];
            #pragma unroll
            for (int i = 0; i < 8; i++)
                #pragma unroll
                for (int j = 0; j < 8; j++)
                    acc[i][j] = fmaf(a[i], b[j], acc[i][j]);
        }
        __syncthreads();
    }
    #pragma unroll
    for (int i = 0; i < 8; i++) {
        int m = m0 + ty*8 + i;
        #pragma unroll
        for (int jv = 0; jv < 2; jv++) {
            int n = n0 + tx*8 + jv*4;
            float4 v;
            v.x = acc[i][jv*4+0]; v.y = acc[i][jv*4+1];
            v.z = acc[i][jv*4+2]; v.w = acc[i][jv*4+3];
            if (bias) {
                float4 bv = *(const float4*)&bias[n];
                v.x += bv.x; v.y += bv.y; v.z += bv.z; v.w += bv.w;
            }
            *(float4*)&Cb[(size_t)m*ldc + n] = v;
        }
    }
}

// ---------------- bf16 tensor-core logits GEMM + fused exp-rowsum ------------
#define PADK 40

__device__ __forceinline__ void ldsm4(uint32_t& r0, uint32_t& r1, uint32_t& r2, uint32_t& r3, uint32_t addr) {
    asm volatile("ldmatrix.sync.aligned.m8n8.x4.shared.b16 {%0,%1,%2,%3}, [%4];"
                 : "=r"(r0), "=r"(r1), "=r"(r2), "=r"(r3) : "r"(addr));
}
__device__ __forceinline__ void mma16816(float* c, const uint32_t* a, const uint32_t* b) {
    asm volatile("mma.sync.aligned.m16n8k16.row.col.f32.bf16.bf16.f32 "
                 "{%0,%1,%2,%3}, {%4,%5,%6,%7}, {%8,%9}, {%0,%1,%2,%3};"
                 : "+f"(c[0]), "+f"(c[1]), "+f"(c[2]), "+f"(c[3])
                 : "r"(a[0]), "r"(a[1]), "r"(a[2]), "r"(a[3]), "r"(b[0]), "r"(b[1]));
}

__global__ __launch_bounds__(256) void k_logits_mma(const float* __restrict__ bias)
{
    __shared__ __nv_bfloat16 As[2][128*PADK];
    __shared__ __nv_bfloat16 Bs[2][128*PADK];
    __shared__ float rsum[128];
    const int Kd = 1024;
    const __nv_bfloat16* A = g_lb;
    const __nv_bfloat16* B = g_Wb;
    int m0 = blockIdx.y*128, n0 = blockIdx.x*128;
    int tid = threadIdx.x;
    int warp = tid >> 5, lane = tid & 31;
    int wm = warp >> 2, wn = warp & 3;

    int srow = tid & 127;
    int shalf = tid >> 7;
    const __nv_bfloat16* gA = A + (size_t)(m0 + srow)*Kd + shalf*16;
    const __nv_bfloat16* gB = B + (size_t)(n0 + srow)*Kd + shalf*16;
    uint32_t sA0 = (uint32_t)__cvta_generic_to_shared(&As[0][srow*PADK + shalf*16]);
    uint32_t sB0 = (uint32_t)__cvta_generic_to_shared(&Bs[0][srow*PADK + shalf*16]);
    const uint32_t bufstrideA = (uint32_t)((char*)&As[1][0] - (char*)&As[0][0]);
    const uint32_t bufstrideB = (uint32_t)((char*)&Bs[1][0] - (char*)&Bs[0][0]);

    float acc[4][4][4];
    #pragma unroll
    for (int i = 0; i < 4; i++)
        #pragma unroll
        for (int j = 0; j < 4; j++)
            #pragma unroll
            for (int k = 0; k < 4; k++) acc[i][j][k] = 0.f;

    int aq = lane >> 3;
    int arow_off = ((aq & 1) << 3) + (lane & 7);
    int acol_off = (aq >> 1) << 3;
    int brow_off = ((aq >> 1) << 3) + (lane & 7);
    int bcol_off = (aq & 1) << 3;

    #pragma unroll
    for (int s = 0; s < 2; s++) {
        asm volatile("cp.async.cg.shared.global [%0], [%1], 16;" ::
                     "r"(sA0 + s*16), "l"(gA + s*8));
        asm volatile("cp.async.cg.shared.global [%0], [%1], 16;" ::
                     "r"(sB0 + s*16), "l"(gB + s*8));
    }
    asm volatile("cp.async.commit_group;");

    const int NIT = Kd/32;
    for (int it = 0; it < NIT; it++) {
        int buf = it & 1;
        if (it + 1 < NIT) {
            uint32_t sa = sA0 + ((it+1)&1)*bufstrideA;
            uint32_t sb = sB0 + ((it+1)&1)*bufstrideB;
            const __nv_bfloat16* ga = gA + (it+1)*32;
            const __nv_bfloat16* gb = gB + (it+1)*32;
            #pragma unroll
            for (int s = 0; s < 2; s++) {
                asm volatile("cp.async.cg.shared.global [%0], [%1], 16;" ::
                             "r"(sa + s*16), "l"(ga + s*8));
                asm volatile("cp.async.cg.shared.global [%0], [%1], 16;" ::
                             "r"(sb + s*16), "l"(gb + s*8));
            }
            asm volatile("cp.async.commit_group;");
            asm volatile("cp.async.wait_group 1;");
        } else {
            asm volatile("cp.async.wait_group 0;");
        }
        __syncthreads();

        #pragma unroll
        for (int kk = 0; kk < 2; kk++) {
            uint32_t aF[4][4], bF[4][2];
            #pragma unroll
            for (int mi = 0; mi < 4; mi++) {
                int row = wm*64 + mi*16 + arow_off;
                int col = kk*16 + acol_off;
                uint32_t ad = (uint32_t)__cvta_generic_to_shared(&As[buf][row*PADK + col]);
                ldsm4(aF[mi][0], aF[mi][1], aF[mi][2], aF[mi][3], ad);
            }
            #pragma unroll
            for (int np = 0; np < 2; np++) {
                int row = wn*32 + np*16 + brow_off;
                int col = kk*16 + bcol_off;
                uint32_t bd = (uint32_t)__cvta_generic_to_shared(&Bs[buf][row*PADK + col]);
                ldsm4(bF[np*2][0], bF[np*2][1], bF[np*2+1][0], bF[np*2+1][1], bd);
            }
            #pragma unroll
            for (int mi = 0; mi < 4; mi++)
                #pragma unroll
                for (int ni = 0; ni < 4; ni++)
                    mma16816(acc[mi][ni], aF[mi], bF[ni]);
        }
        __syncthreads();
    }

    if (tid < 128) rsum[tid] = 0.f;
    __syncthreads();

    int g = lane >> 2, tg = lane & 3;
    #pragma unroll
    for (int mi = 0; mi < 4; mi++) {
        int r0l = wm*64 + mi*16 + g;
        int r1l = r0l + 8;
        float rp0 = 0.f, rp1 = 0.f;
        #pragma unroll
        for (int ni = 0; ni < 4; ni++) {
            int n = n0 + wn*32 + ni*8 + tg*2;
            float2 bv = *(const float2*)&bias[n];
            float v0 = acc[mi][ni][0] + bv.x;
            float v1 = acc[mi][ni][1] + bv.y;
            float v2 = acc[mi][ni][2] + bv.x;
            float v3 = acc[mi][ni][3] + bv.y;
            *(__nv_bfloat162*)&g_logb[(size_t)(m0 + r0l)*VOCAB + n] =
                __nv_bfloat162(__float2bfloat16(v0), __float2bfloat16(v1));
            *(__nv_bfloat162*)&g_logb[(size_t)(m0 + r1l)*VOCAB + n] =
                __nv_bfloat162(__float2bfloat16(v2), __float2bfloat16(v3));
            rp0 += fexp(v0) + fexp(v1);
            rp1 += fexp(v2) + fexp(v3);
        }
        atomicAdd(&rsum[r0l], rp0);
        atomicAdd(&rsum[r1l], rp1);
    }
    __syncthreads();
    if (tid < 128) atomicAdd(&g_rowsum[m0 + tid], rsum[tid]);
}

// ---------------- persistent recurrence (pipelined, f32x2 GEMV) --------------
__global__ __launch_bounds__(256) void k_recur(
    const float* __restrict__ W_ih, const float* __restrict__ W_hh,
    const float* __restrict__ b_ih, const float* __restrict__ b_hh,
    const int* __restrict__ entlens)
{
    extern __shared__ float sx[];
    float4* sa = (float4*)sx;
    float4* sk = (float4*)(sx + 4096);
    float4* sh = (float4*)(sx + 8192);
    float* gsh = sx + 12288;
    __shared__ float cxs[48];
    __shared__ float sc[NEN];

    int tid = threadIdx.x;
    int blk = blockIdx.x;
    int warp = tid >> 5, lane = tid & 31;
    bool isAtt = (blk >= 96);

    int ng = 0, g0 = 0;
    const float4 *wa0=nullptr,*wa1=nullptr,*wa2=nullptr,*wb0=nullptr,*wb1=nullptr,*wb2=nullptr;
    float bias0=0.f, bias1=0.f, bias2=0.f;
    bool has2 = false;
    int ab = 0, ah = 0, alen = 0;

    if (!isAtt) {
        ng = (blk < 32) ? 6 : 5;
        g0 = (blk < 32) ? blk*6 : 192 + (blk - 32)*5;
        int nrows = 4*ng;
        int lr0 = warp, lr1 = warp + 8, lr2 = warp + 16;
        has2 = (lr2 < nrows);
        int r0 = (lr0 & 3)*512 + g0 + (lr0 >> 2);
        int r1 = (lr1 & 3)*512 + g0 + (lr1 >> 2);
        int r2 = has2 ? ((lr2 & 3)*512 + g0 + (lr2 >> 2)) : r0;
        wa0 = (const float4*)(W_ih + (size_t)r0*1024);
        wa1 = (const float4*)(W_ih + (size_t)r1*1024);
        wa2 = (const float4*)(W_ih + (size_t)r2*1024);
        wb0 = (const float4*)(W_hh + (size_t)r0*512);
        wb1 = (const float4*)(W_hh + (size_t)r1*512);
        wb2 = (const float4*)(W_hh + (size_t)r2*512);
        bias0 = b_ih[r0] + b_hh[r0];
        bias1 = b_ih[r1] + b_hh[r1];
        bias2 = has2 ? (b_ih[r2] + b_hh[r2]) : 0.f;
        if (tid < ng*8)
            cxs[tid] = g_cx[(tid & 7)*HH + g0 + (tid >> 3)];
    } else {
        ab = (blk - 96) >> 2;
        ah = (blk - 96) & 3;
        alen = __ldg(&entlens[ab]);
    }

    if (!isAtt) {
        for (int t = 0; t < TT; t++) {
            // stage k(t) packed — NO sync dependency
            for (int i = tid; i < 512; i += 256) {
                int p = i >> 7, j4 = i & 127;
                float4 va = ldcg4(g_kseq + (size_t)((2*p  )*TT + t)*HH + j4*4);
                float4 vb = ldcg4(g_kseq + (size_t)((2*p+1)*TT + t)*HH + j4*4);
                sk[p*256 + j4*2 + 0] = make_float4(va.x, vb.x, va.y, vb.y);
                sk[p*256 + j4*2 + 1] = make_float4(va.z, vb.z, va.w, vb.w);
            }
            __syncthreads();

            unsigned long long accA[4], accB[4], accC[4];
            #pragma unroll
            for (int p = 0; p < 4; p++) { accA[p] = 0ull; accB[p] = 0ull; accC[p] = 0ull; }

            // k-part (W_ih cols 512..1023) — before any waits
            #pragma unroll
            for (int i = 0; i < 4; i++) {
                float4 w0 = wa0[128 + i*32 + lane];
                float4 w1 = wa1[128 + i*32 + lane];
                float4 w2 = wa2[128 + i*32 + lane];
                unsigned long long w0x=pack2(w0.x),w0y=pack2(w0.y),w0z=pack2(w0.z),w0w=pack2(w0.w);
                unsigned long long w1x=pack2(w1.x),w1y=pack2(w1.y),w1z=pack2(w1.z),w1w=pack2(w1.w);
                unsigned long long w2x=pack2(w2.x),w2y=pack2(w2.y),w2z=pack2(w2.z),w2w=pack2(w2.w);
                #pragma unroll
                for (int p = 0; p < 4; p++) {
                    ulonglong2 x01 = *(const ulonglong2*)&sk[p*256 + (i*32+lane)*2];
                    ulonglong2 x23 = *(const ulonglong2*)&sk[p*256 + (i*32+lane)*2 + 1];
                    fma2(accA[p], w0x, x01.x); fma2(accA[p], w0y, x01.y);
                    fma2(accA[p], w0z, x23.x); fma2(accA[p], w0w, x23.y);
                    fma2(accB[p], w1x, x01.x); fma2(accB[p], w1y, x01.y);
                    fma2(accB[p], w1z, x23.x); fma2(accB[p], w1w, x23.y);
                    fma2(accC[p], w2x, x01.x); fma2(accC[p], w2y, x01.y);
                    fma2(accC[p], w2z, x23.x); fma2(accC[p], w2w, x23.y);
                }
            }

            if (t) {
                if (tid == 0) { unsigned tgt = 96u*t; while (ld_poll(&g_c1) < tgt) {} }
            }
            __syncthreads();
            const float* hxin = g_hx2 + ((t+1)&1)*(BB*HH);
            for (int i = tid; i < 512; i += 256) {
                int p = i >> 7, j4 = i & 127;
                float4 va = ldcg4(hxin + (size_t)(2*p  )*HH + j4*4);
                float4 vb = ldcg4(hxin + (size_t)(2*p+1)*HH + j4*4);
                sh[p*256 + j4*2 + 0] = make_float4(va.x, vb.x, va.y, vb.y);
                sh[p*256 + j4*2 + 1] = make_float4(va.z, vb.z, va.w, vb.w);
            }
            __syncthreads();

            // hx-part (W_hh)
            #pragma unroll
            for (int i = 0; i < 4; i++) {
                float4 w0 = wb0[i*32 + lane];
                float4 w1 = wb1[i*32 + lane];
                float4 w2 = wb2[i*32 + lane];
                unsigned long long w0x=pack2(w0.x),w0y=pack2(w0.y),w0z=pack2(w0.z),w0w=pack2(w0.w);
                unsigned long long w1x=pack2(w1.x),w1y=pack2(w1.y),w1z=pack2(w1.z),w1w=pack2(w1.w);
                unsigned long long w2x=pack2(w2.x),w2y=pack2(w2.y),w2z=pack2(w2.z),w2w=pack2(w2.w);
                #pragma unroll
                for (int p = 0; p < 4; p++) {
                    ulonglong2 x01 = *(const ulonglong2*)&sh[p*256 + (i*32+lane)*2];
                    ulonglong2 x23 = *(const ulonglong2*)&sh[p*256 + (i*32+lane)*2 + 1];
                    fma2(accA[p], w0x, x01.x); fma2(accA[p], w0y, x01.y);
                    fma2(accA[p], w0z, x23.x); fma2(accA[p], w0w, x23.y);
                    fma2(accB[p], w1x, x01.x); fma2(accB[p], w1y, x01.y);
                    fma2(accB[p], w1z, x23.x); fma2(accB[p], w1w, x23.y);
                    fma2(accC[p], w2x, x01.x); fma2(accC[p], w2y, x01.y);
                    fma2(accC[p], w2z, x23.x); fma2(accC[p], w2w, x23.y);
                }
            }

            if (t) {
                if (tid == 0) { unsigned tgt = 32u*t; while (ld_poll(&g_c2) < tgt) {} }
            }
            __syncthreads();
            for (int i = tid; i < 512; i += 256) {
                int p = i >> 7, j4 = i & 127;
                float4 va = ldcg4(g_a + (size_t)(2*p  )*HH + j4*4);
                float4 vb = ldcg4(g_a + (size_t)(2*p+1)*HH + j4*4);
                sa[p*256 + j4*2 + 0] = make_float4(va.x, vb.x, va.y, vb.y);
                sa[p*256 + j4*2 + 1] = make_float4(va.z, vb.z, va.w, vb.w);
            }
            __syncthreads();

            // a-part (W_ih cols 0..511)
            #pragma unroll
            for (int i = 0; i < 4; i++) {
                float4 w0 = wa0[i*32 + lane];
                float4 w1 = wa1[i*32 + lane];
                float4 w2 = wa2[i*32 + lane];
                unsigned long long w0x=pack2(w0.x),w0y=pack2(w0.y),w0z=pack2(w0.z),w0w=pack2(w0.w);
                unsigned long long w1x=pack2(w1.x),w1y=pack2(w1.y),w1z=pack2(w1.z),w1w=pack2(w1.w);
                unsigned long long w2x=pack2(w2.x),w2y=pack2(w2.y),w2z=pack2(w2.z),w2w=pack2(w2.w);
                #pragma unroll
                for (int p = 0; p < 4; p++) {
                    ulonglong2 x01 = *(const ulonglong2*)&sa[p*256 + (i*32+lane)*2];
                    ulonglong2 x23 = *(const ulonglong2*)&sa[p*256 + (i*32+lane)*2 + 1];
                    fma2(accA[p], w0x, x01.x); fma2(accA[p], w0y, x01.y);
                    fma2(accA[p], w0z, x23.x); fma2(accA[p], w0w, x23.y);
                    fma2(accB[p], w1x, x01.x); fma2(accB[p], w1y, x01.y);
                    fma2(accB[p], w1z, x23.x); fma2(accB[p], w1w, x23.y);
                    fma2(accC[p], w2x, x01.x); fma2(accC[p], w2y, x01.y);
                    fma2(accC[p], w2z, x23.x); fma2(accC[p], w2w, x23.y);
                }
            }

            float a0[8], a1[8], a2[8];
            #pragma unroll
            for (int p = 0; p < 4; p++) {
                float2 u;
                u = unpack2(accA[p]); a0[2*p] = u.x; a0[2*p+1] = u.y;
                u = unpack2(accB[p]); a1[2*p] = u.x; a1[2*p+1] = u.y;
                u = unpack2(accC[p]); a2[2*p] = u.x; a2[2*p+1] = u.y;
            }
            #pragma unroll
            for (int b = 0; b < 8; b++) {
                float v0 = a0[b], v1 = a1[b], v2 = a2[b];
                #pragma unroll
                for (int o = 16; o; o >>= 1) {
                    v0 += __shfl_xor_sync(0xffffffffu, v0, o);
                    v1 += __shfl_xor_sync(0xffffffffu, v1, o);
                    v2 += __shfl_xor_sync(0xffffffffu, v2, o);
                }
                if (lane == 0) {
                    gsh[warp*8 + b]     = v0 + bias0;
                    gsh[(warp+8)*8 + b] = v1 + bias1;
                    if (has2) gsh[(warp+16)*8 + b] = v2 + bias2;
                }
            }
            __syncthreads();
            float hxv = 0.f; int hb = 0, hh = 0;
            if (tid < ng*8) {
                int lg = tid >> 3; hb = tid & 7;
                hh = g0 + lg;
                float gi = gsh[(lg*4 + 0)*8 + hb];
                float gf = gsh[(lg*4 + 1)*8 + hb];
                float gg = gsh[(lg*4 + 2)*8 + hb];
                float go = gsh[(lg*4 + 3)*8 + hb];
                float c  = sigf(gf)*cxs[tid] + sigf(gi)*tanhf(gg);
                hxv = sigf(go)*tanhf(c);
                cxs[tid] = c;
                g_hx2[(t&1)*(BB*HH) + hb*HH + hh] = hxv;
            }
            __syncthreads();
            if (tid == 0) red_add(&g_c1);
            if (tid < ng*8) {
                size_t li = ((size_t)(hb*TT + t))*1024 + hh;
                g_l[li]  = hxv;
                g_lb[li] = __float2bfloat16(hxv);
            }
        }
    } else {
        const float* g_V = g_KV + BB*NEN*HH;
        float* hxs = (float*)sh;
        for (int t = 0; t < TT; t++) {
            if (tid == 0) { unsigned tgt = 96u*(t+1); while (ld_poll(&g_c1) < tgt) {} }
            __syncthreads();

            const float* hxin = g_hx2 + (t&1)*(BB*HH) + (size_t)ab*HH;
            for (int i = tid; i < 128; i += 256)
                ((float4*)hxs)[i] = ldcg4(hxin + i*4);
            __syncthreads();

            {   // scores: 64 n x 4 threads (P slice L1-resident)
                int n = tid >> 2, sub = tid & 3;
                const float4* p4 = (const float4*)(g_P + ((size_t)(ah*512 + ab*64 + n))*512 + sub*128);
                const float4* x4 = (const float4*)(hxs + sub*128);
                float acc = 0.f;
                #pragma unroll 8
                for (int i = 0; i < 32; i++) {
                    float4 p = __ldg(&p4[i]), x = x4[i];
                    acc = fmaf(p.x,x.x, fmaf(p.y,x.y, fmaf(p.z,x.z, fmaf(p.w,x.w, acc))));
                }
                acc += __shfl_xor_sync(0xffffffffu, acc, 1);
                acc += __shfl_xor_sync(0xffffffffu, acc, 2);
                if (sub == 0)
                    sc[n] = (n <= alen) ? acc * 0.04419417382415922f : -1e30f;
            }
            __syncthreads();
            if (tid < 32) {
                // |score| ≲ 2 ⇒ no max-subtraction needed; exp(-1e30) → 0 (masked)
                float e0 = __expf(sc[tid]), e1 = __expf(sc[tid + 32]);
                float s2 = e0 + e1;
                #pragma unroll
                for (int o = 16; o; o >>= 1) s2 += __shfl_xor_sync(0xffffffffu, s2, o);
                float inv = 1.0f / s2;
                sc[tid]      = e0 * inv;
                sc[tid + 32] = e1 * inv;
            }
            __syncthreads();
            float av = 0.f; int hv = 0; bool wr = false;
            {   // a = attn . V (V slice L1-resident)
                int d = tid >> 1, half = tid & 1;
                const float* vb = g_V + ((size_t)(ab*64 + half*32))*512 + ah*128 + d;
                float acc = 0.f;
                #pragma unroll 8
                for (int n2 = 0; n2 < 32; n2++)
                    acc = fmaf(sc[half*32 + n2], __ldg(&vb[(size_t)n2*512]), acc);
                float other = __shfl_xor_sync(0xffffffffu, acc, 1);
                if (half == 0) {
                    av = acc + other;
                    hv = ah*128 + d;
                    wr = true;
                    g_a[ab*HH + hv] = av;
                }
            }
            __syncthreads();
            if (tid == 0) red_add(&g_c2);
            if (wr) {
                size_t li = ((size_t)(ab*TT + t))*1024 + 512 + hv;
                g_l[li]  = av;
                g_lb[li] = __float2bfloat16(av);
            }
        }
    }
}

__global__ __launch_bounds__(256) void k_switch(
    const float* __restrict__ sw_W, const float* __restrict__ sw_b)
{
    int r = blockIdx.x*8 + (threadIdx.x >> 5);
    int lane = threadIdx.x & 31;
    const float4* l4 = (const float4*)(g_l + (size_t)r*1024);
    const float4* w4 = (const float4*)sw_W;
    float acc = 0.f;
    #pragma unroll
    for (int i = 0; i < 8; i++) {
        float4 a = l4[i*32 + lane], w = w4[i*32 + lane];
        acc = fmaf(a.x,w.x, fmaf(a.y,w.y, fmaf(a.z,w.z, fmaf(a.w,w.w, acc))));
    }
    #pragma unroll
    for (int o = 16; o; o >>= 1) acc += __shfl_xor_sync(0xffffffffu, acc, o);
    if (lane == 0) g_s[r] = sigf(acc + sw_b[0]);
}

__global__ __launch_bounds__(64) void k_ptr(
    const float* __restrict__ ents, const int* __restrict__ entlens,
    float* __restrict__ out, int write_tail)
{
    __shared__ float ds[HH];
    __shared__ float red[2];
    int r = blockIdx.x;
    int b = r >> 8;
    int tid = threadIdx.x;
    for (int i = tid; i < HH; i += 64) ds[i] = g_dec[(size_t)r*HH + i];
    __syncthreads();
    int len = entlens[b];
    float sv = -1e30f;
    if (tid <= len) {
        float acc = 0.f;
        const float4* e4 = (const float4*)(ents + (size_t)(b*NEN + tid)*HH);
        const float4* d4 = (const float4*)ds;
        #pragma unroll 8
        for (int i = 0; i < HH/4; i++) {
            float4 ev = e4[i], dv = d4[i];
            acc = fmaf(ev.x,dv.x, fmaf(ev.y,dv.y, fmaf(ev.z,dv.z, fmaf(ev.w,dv.w, acc))));
        }
        sv = acc;
    }
    float v = sv;
    #pragma unroll
    for (int o = 16; o; o >>= 1) v = fmaxf(v, __shfl_xor_sync(0xffffffffu, v, o));
    if ((tid & 31) == 0) red[tid >> 5] = v;
    __syncthreads();
    float m = fmaxf(red[0], red[1]);
    float e = (tid <= len) ? __expf(sv - m) : 0.f;
    float s2 = e;
    #pragma unroll
    for (int o = 16; o; o >>= 1) s2 += __shfl_xor_sync(0xffffffffu, s2, o);
    if ((tid & 31) == 0) red[tid >> 5] = s2;
    __syncthreads();
    float inv = 1.0f / (red[0] + red[1]);
    float s = g_s[r];
    float z = e * inv * (1.0f - s);
    out[(size_t)r*LDO + VOCAB + tid] = flog(z + 1e-6f);
    if (write_tail) out[(size_t)NROWS*LDO + (size_t)r*NEN + tid] = z;
}

__global__ void k_rowc() {
    int r = blockIdx.x*256 + threadIdx.x;
    if (r < NROWS) g_c[r] = g_s[r] / g_rowsum[r];
}

__global__ __launch_bounds__(256) void k_final(float* __restrict__ out) {
    int r = blockIdx.x;
    float c = g_c[r];
    const __nv_bfloat162* src = (const __nv_bfloat162*)(g_logb + (size_t)r*VOCAB);
    float* dst = out + (size_t)r*LDO;
    for (int i = threadIdx.x; i < VOCAB/2; i += 256) {
        __nv_bfloat162 p = src[i];
        float2 o;
        o.x = flog(fmaf(fexp(__bfloat162float(p.x)), c, 1e-6f));
        o.y = flog(fmaf(fexp(__bfloat162float(p.y)), c, 1e-6f));
        *(float2*)&dst[i*2] = o;
    }
}

extern "C" void kernel_launch(void* const* d_in, const int* in_sizes, int n_in,
                              void* d_out, int out_size)
{
    const int*   outp    = (const int*)  d_in[0];
    const float* ents    = (const float*)d_in[1];
    const int*   entlens = (const int*)  d_in[2];
    const float* emb     = (const float*)d_in[3];
    const float* W_ih    = (const float*)d_in[4];
    const float* W_hh    = (const float*)d_in[5];
    const float* b_ih    = (const float*)d_in[6];
    const float* b_hh    = (const float*)d_in[7];
    const float* Wq      = (const float*)d_in[8];
    const float* Wk      = (const float*)d_in[9];
    const float* Wv      = (const float*)d_in[10];
    const float* out_W   = (const float*)d_in[11];
    const float* out_b   = (const float*)d_in[12];
    const float* sw_W    = (const float*)d_in[13];
    const float* sw_b    = (const float*)d_in[14];
    const float* mattn_W = (const float*)d_in[15];
    const float* mattn_b = (const float*)d_in[16];
    float* out = (float*)d_out;

    static int smem_set = 0;
    if (!smem_set) {
        cudaFuncSetAttribute(k_recur, cudaFuncAttributeMaxDynamicSharedMemorySize, 64*1024);
        smem_set = 1;
    }
    const int recur_smem = (3*4096 + 192) * 4;

    float *g_KV_p, *g_P_p, *g_Wqt_p, *g_l_p, *g_dec_p;
    cudaGetSymbolAddress((void**)&g_KV_p, g_KV);
    cudaGetSymbolAddress((void**)&g_P_p, g_P);
    cudaGetSymbolAddress((void**)&g_Wqt_p, g_Wqt);
    cudaGetSymbolAddress((void**)&g_l_p, g_l);
    cudaGetSymbolAddress((void**)&g_dec_p, g_dec);

    // ncu profiles my 4th launch → put k_recur there
    k_init<<<NROWS + 12 + 256, 512>>>(ents, emb, outp, Wq);             // 1
    k_sgemm<<<dim3(4,4,2), 256>>>(ents, 512, 0, Wk, Wv, 512, 0, 1,      // 2 (K+V)
                                  nullptr, g_KV_p, 512, BB*NEN*HH, 512);
    k_sgemm<<<dim3(4,4,4), 256>>>(g_KV_p, 512, 128, g_Wqt_p, g_Wqt_p, 512, 128, 0,  // 3 (P)
                                  nullptr, g_P_p, 512, 512*512, 128);
    k_recur<<<GRIDN, 256, recur_smem>>>(W_ih, W_hh, b_ih, b_hh, entlens); // 4 ← ncu

    k_cvtw<<<VOCAB*1024/(256*4), 256>>>(out_W);
    k_switch<<<NROWS/8, 256>>>(sw_W, sw_b);
    k_sgemm<<<dim3(4,16,1), 256>>>(g_l_p, 1024, 0, mattn_W, mattn_W, 1024, 0, 0,
                                   mattn_b, g_dec_p, 512, 0, 1024);
    k_logits_mma<<<dim3(VOCAB/128, NROWS/128), 256>>>(out_b);
    k_rowc<<<8, 256>>>();
    int write_tail = (out_size >= NROWS*LDO + NROWS*NEN) ? 1 : 0;
    k_ptr<<<NROWS, 64>>>(ents, entlens, out, write_tail);
    k_final<<<NROWS, 256>>>(out);
}